// round 12
// baseline (speedup 1.0000x reference)
#include <cuda_runtime.h>
#include <cuda_fp16.h>
#include <math.h>
#include <stdint.h>

#define BATCH 8
#define UPC   256
#define HH    256
#define WWD   256
#define HWN   65536
#define MTOT  (BATCH*HWN)   // 524288

// ---------------- scratch (static device globals; allocation-free) ----------------
__device__ __half g_xuPh[(size_t)BATCH*HWN*UPC];   // [b][h][c8][w][32] pair-interleaved half
__device__ float  g_h1 [(size_t)MTOT*128];         // mlp1 out fp32 (LN stats + identity)
__device__ __half g_lnh[(size_t)MTOT*128];         // layernorm out, interleaved half
__device__ __half g_w9ph[9*8*128*32];              // conv weights [off][c8][co][32] interleaved
__device__ __half g_w1h [128*256];                 // mlp1 W^T [n][k-interleaved]
__device__ __half g_w3comb[128*128];               // w3_1*w3_2*w3_3, [n][k-interleaved]
__device__ __half g_w4comb[128*128];
__device__ float  g_wtmp[128*64];
__device__ __half g_lnwh[(size_t)HWN*128];
__device__ __half g_lnbh[(size_t)HWN*128];
__device__ float  g_bias1[BATCH*128];
__device__ float  g_bias3c[BATCH*128];
__device__ float  g_bias4c[BATCH*128];
__device__ float  g_part[BATCH*512*2];
__device__ float  g_stats[BATCH*2];

// channel c (0..31) -> half slot within 32-half chunk (pair-interleaved)
__device__ __forceinline__ int lam32(int c){
    int g  = c >> 4;
    int kp = (c & 15) >> 1;
    int o  = c & 1;
    return 8*(kp & 3) + 4*g + 2*(kp >> 2) + o;
}

__device__ __forceinline__ void mma_fp16(float c[4],
        uint32_t a0, uint32_t a1, uint32_t a2, uint32_t a3,
        uint32_t b0, uint32_t b1){
    asm volatile(
        "mma.sync.aligned.m16n8k16.row.col.f32.f16.f16.f32 "
        "{%0,%1,%2,%3}, {%4,%5,%6,%7}, {%8,%9}, {%0,%1,%2,%3};"
        : "+f"(c[0]), "+f"(c[1]), "+f"(c[2]), "+f"(c[3])
        : "r"(a0), "r"(a1), "r"(a2), "r"(a3), "r"(b0), "r"(b1));
}

__device__ __forceinline__ void cp16(uint32_t dst, const void* src, int bytes){
    asm volatile("cp.async.cg.shared.global [%0], [%1], 16, %2;"
                 :: "r"(dst), "l"(src), "r"(bytes));
}
__device__ __forceinline__ void cp_commit(){ asm volatile("cp.async.commit_group;"); }
__device__ __forceinline__ void cp_wait1(){ asm volatile("cp.async.wait_group 1;"); }
__device__ __forceinline__ void cp_wait0(){ asm volatile("cp.async.wait_group 0;"); }

// ---------------- prep kernels ----------------
__global__ void prep_w9h(const float* __restrict__ cw){
    int i = blockIdx.x*256 + threadIdx.x;
    if (i < 9*8*128*32){
        int c   = i & 31;
        int co  = (i >> 5) & 127;
        int c8  = (i >> 12) & 7;
        int off = i >> 15;
        int ci  = c8*32 + c;
        g_w9ph[(((off*8 + c8)*128 + co)*32) + lam32(c)] =
            __float2half_rn(cw[(co*256 + ci)*9 + off]);
    }
}

__global__ void prep_w1h(const float* __restrict__ w1){
    int i = blockIdx.x*256 + threadIdx.x;
    if (i < 128*256){
        int k = i & 255, n = i >> 8;
        g_w1h[n*256 + (k>>5)*32 + lam32(k & 31)] = __float2half_rn(w1[k*128 + n]);
    }
}

__global__ void combine_w12(const float* __restrict__ w1, const float* __restrict__ w2){
    int i = blockIdx.x*256 + threadIdx.x;
    if (i < 8192){
        int k = i >> 6, j = i & 63;
        float s = 0.f;
        #pragma unroll 8
        for (int t = 0; t < 64; t++) s += w1[k*64 + t]*w2[t*64 + j];
        g_wtmp[k*64 + j] = s;
    }
}
__global__ void combine_w3(const float* __restrict__ w3, __half* __restrict__ o){
    int i = blockIdx.x*256 + threadIdx.x;
    if (i < 16384){
        int k = i >> 7, n = i & 127;
        float s = 0.f;
        #pragma unroll 8
        for (int j = 0; j < 64; j++) s += g_wtmp[k*64 + j]*w3[j*128 + n];
        o[n*128 + (k>>5)*32 + lam32(k & 31)] = __float2half_rn(s);
    }
}
__global__ void combine_bias(const float* __restrict__ sv,
                             const float* __restrict__ w1, const float* __restrict__ b1,
                             const float* __restrict__ w2, const float* __restrict__ b2,
                             const float* __restrict__ w3, const float* __restrict__ b3,
                             float* __restrict__ ob){
    __shared__ float v[64], u[64];
    int t = threadIdx.x;
    for (int b = 0; b < BATCH; b++){
        float sb = sv[b];
        if (t < 64) v[t] = b1[t] + sb*w1[128*64 + t];
        __syncthreads();
        if (t < 64){
            float s = b2[t];
            #pragma unroll 8
            for (int i = 0; i < 64; i++) s += v[i]*w2[i*64 + t];
            u[t] = s;
        }
        __syncthreads();
        float s = b3[t];
        #pragma unroll 8
        for (int j = 0; j < 64; j++) s += u[j]*w3[j*128 + t];
        ob[b*128 + t] = s;
        __syncthreads();
    }
}

__global__ void prep_bias1(const float* __restrict__ s,
                           const float* __restrict__ m1w, const float* __restrict__ m1b){
    int t = threadIdx.x;
    if (t < 128)
        for (int b = 0; b < BATCH; b++)
            g_bias1[b*128+t] = m1b[t] + s[b]*m1w[256*128 + t];
}

__global__ void prep_lnh(const float* __restrict__ lnw, const float* __restrict__ lnb){
    size_t e = ((size_t)blockIdx.x*256 + threadIdx.x)*4;
    float4 w = *(const float4*)&lnw[e];
    float4 b = *(const float4*)&lnb[e];
    *(__half2*)(g_lnwh + e)     = __floats2half2_rn(w.x, w.y);
    *(__half2*)(g_lnwh + e + 2) = __floats2half2_rn(w.z, w.w);
    *(__half2*)(g_lnbh + e)     = __floats2half2_rn(b.x, b.y);
    *(__half2*)(g_lnbh + e + 2) = __floats2half2_rn(b.z, b.w);
}

// ---------------- fused bicubic 2x upsample -> interleaved half (g_xuPh) ----------------
__global__ __launch_bounds__(256) void upsample_fused_kernel(const float* __restrict__ x){
    __shared__ __half sm[2][256][32];
    int kh = blockIdx.x, c8 = blockIdx.y, b = blockIdx.z;
    int tid = threadIdx.x;
    int lane = tid & 31, warp = tid >> 5;

    int rr[5];
    #pragma unroll
    for (int i = 0; i < 5; i++){
        int r = kh - 2 + i; rr[i] = min(max(r,0),127);
    }
    const float we0=-0.03515625f, we1=0.26171875f, we2=0.87890625f, we3=-0.10546875f;
    const float wo0=-0.10546875f, wo1=0.87890625f, wo2=0.26171875f, wo3=-0.03515625f;

    #pragma unroll
    for (int q = 0; q < 4; q++){
        int cg = warp*4 + q;
        int c  = c8*32 + cg;
        const float* xp = x + ((size_t)(b*256 + c))*16384;
        int slot = lam32(cg);
        #pragma unroll
        for (int j = 0; j < 4; j++){
            int kw = lane + 32*j;
            int cc[5];
            #pragma unroll
            for (int i = 0; i < 5; i++){
                int cw_ = kw - 2 + i; cc[i] = min(max(cw_,0),127);
            }
            float he[5], ho[5];
            #pragma unroll
            for (int i = 0; i < 5; i++){
                const float* row = xp + rr[i]*128;
                float v0=row[cc[0]], v1=row[cc[1]], v2=row[cc[2]], v3=row[cc[3]], v4=row[cc[4]];
                he[i] = we0*v0 + we1*v1 + we2*v2 + we3*v3;
                ho[i] = wo0*v1 + wo1*v2 + wo2*v3 + wo3*v4;
            }
            float o00 = we0*he[0]+we1*he[1]+we2*he[2]+we3*he[3];
            float o01 = we0*ho[0]+we1*ho[1]+we2*ho[2]+we3*ho[3];
            float o10 = wo0*he[1]+wo1*he[2]+wo2*he[3]+wo3*he[4];
            float o11 = wo0*ho[1]+wo1*ho[2]+wo2*ho[3]+wo3*ho[4];
            sm[0][2*kw  ][slot] = __float2half_rn(o00);
            sm[0][2*kw+1][slot] = __float2half_rn(o01);
            sm[1][2*kw  ][slot] = __float2half_rn(o10);
            sm[1][2*kw+1][slot] = __float2half_rn(o11);
        }
    }
    __syncthreads();

    __half* out0 = g_xuPh + ((size_t)((b*256 + 2*kh    )*8 + c8))*8192;
    __half* out1 = g_xuPh + ((size_t)((b*256 + 2*kh + 1)*8 + c8))*8192;
    const uint4* s0 = (const uint4*)&sm[0][0][0];
    const uint4* s1 = (const uint4*)&sm[1][0][0];
    #pragma unroll
    for (int p = 0; p < 4; p++){
        ((uint4*)out0)[p*256 + tid] = s0[p*256 + tid];
        ((uint4*)out1)[p*256 + tid] = s1[p*256 + tid];
    }
}

// ---------------- FUSED conv 3x3 + y-ingest + mlp1 (fp16 mma) ----------------
// SMEM plan (dynamic, 81920 B):
//   conv phase : Ab[2] @0/@8320 (8320 each), Bb[2] @16640/@41216 (24576 each)
//   y stage    : YST @65536 (16384 B fp32, one 32ch x 128w chunk)
//   mlp1 phase : A-tile 8 chunks @0 (65536), B double buffer @65536/@73728
#define CM_SMEM 81920

__global__ __launch_bounds__(128, 2) void conv_mlp1_kernel(const float* __restrict__ convb,
                                                           const float* __restrict__ y){
    extern __shared__ char dsm[];
    __shared__ float shs[128], shs2[128];
    char* const Ab[2] = {dsm, dsm + 8320};
    char* const Bb[2] = {dsm + 16640, dsm + 41216};
    uint32_t Au[2], Bu[2];
    Au[0] = (uint32_t)__cvta_generic_to_shared(Ab[0]);
    Au[1] = (uint32_t)__cvta_generic_to_shared(Ab[1]);
    Bu[0] = (uint32_t)__cvta_generic_to_shared(Bb[0]);
    Bu[1] = (uint32_t)__cvta_generic_to_shared(Bb[1]);
    char* Am  = dsm;                      // mlp1 A tile (8 chunks of 8192)
    char* YST = dsm + 65536;              // fp32 y staging (16 KB)
    uint32_t YSTU = (uint32_t)__cvta_generic_to_shared(YST);
    char* const Bm[2] = {dsm + 65536, dsm + 73728};
    uint32_t BmU[2];
    BmU[0] = (uint32_t)__cvta_generic_to_shared(Bm[0]);
    BmU[1] = (uint32_t)__cvta_generic_to_shared(Bm[1]);

    int bx = blockIdx.x;
    int w0 = (bx & 1)*128;
    int h  = (bx >> 1) & 255;
    int b  = bx >> 9;
    int m0 = b*65536 + h*256 + w0;        // mlp1 row base
    int tid = threadIdx.x;
    int wid = tid >> 5, lane = tid & 31;
    int wm = wid & 1, wn = wid >> 1;
    int lr = lane >> 2, lc = lane & 3;

    int hhs[3], off3s[3], nh = 0;
    #pragma unroll
    for (int dh = -1; dh <= 1; dh++){
        int hh = h + dh;
        if (hh >= 0 && hh < HH){ hhs[nh] = hh; off3s[nh] = (dh+1)*3; nh++; }
    }
    int nch = nh*8;

    float acc[4][8][4];
    #pragma unroll
    for (int mi = 0; mi < 4; mi++)
        #pragma unroll
        for (int ni = 0; ni < 8; ni++)
            #pragma unroll
            for (int r = 0; r < 4; r++) acc[mi][ni][r] = 0.f;

    auto fill = [&](int i, int s){
        int ih = i >> 3, c8 = i & 7;
        const __half* aplane = g_xuPh + ((size_t)((b*256 + hhs[ih])*8 + c8))*8192;
        #pragma unroll
        for (int p = 0; p < 5; p++){
            int idx = tid + p*128;
            if (idx < 520){
                int row = idx >> 2, t = idx & 3;
                int w_in = w0 - 1 + row;
                int ok = (w_in >= 0 && w_in < WWD) ? 16 : 0;
                int wc = min(max(w_in, 0), WWD-1);
                cp16(Au[s] + row*64 + (16*t ^ ((row & 1) << 5)),
                     aplane + wc*32 + t*8, ok);
            }
        }
        const __half* wb = g_w9ph + ((size_t)(off3s[ih]*8 + c8))*128*32;
        #pragma unroll
        for (int p = 0; p < 12; p++){
            int idx = tid + p*128;
            int row = idx >> 2, t = idx & 3;
            int dwi = row >> 7, co = row & 127;
            cp16(Bu[s] + row*64 + (16*t ^ ((row & 1) << 5)),
                 wb + ((size_t)dwi*8*128*32) + co*32 + t*8, 16);
        }
    };

    // ===== conv mainloop =====
    fill(0, 0);
    cp_commit();

    for (int i = 0; i < nch; i++){
        int s = i & 1;
        if (i + 1 < nch){ fill(i+1, s^1); cp_commit(); cp_wait1(); }
        else cp_wait0();
        __syncthreads();

        char* As = Ab[s];
        char* Bs = Bb[s];
        #pragma unroll
        for (int dwi = 0; dwi < 3; dwi++){
            uint4 bf[8];
            #pragma unroll
            for (int ni = 0; ni < 8; ni++){
                int brow = dwi*128 + wn*64 + ni*8 + lr;
                bf[ni] = *(const uint4*)(Bs + brow*64 + (16*lc ^ ((brow & 1) << 5)));
            }
            #pragma unroll
            for (int mi = 0; mi < 4; mi++){
                int ar0 = wm*64 + mi*16 + lr + dwi;
                int ar1 = ar0 + 8;
                uint4 A1 = *(const uint4*)(As + ar0*64 + (16*lc ^ ((ar0 & 1) << 5)));
                uint4 A2 = *(const uint4*)(As + ar1*64 + (16*lc ^ ((ar1 & 1) << 5)));
                #pragma unroll
                for (int ni = 0; ni < 8; ni++){
                    mma_fp16(acc[mi][ni], A1.x, A2.x, A1.y, A2.y, bf[ni].x, bf[ni].y);
                    mma_fp16(acc[mi][ni], A1.z, A2.z, A1.w, A2.w, bf[ni].z, bf[ni].w);
                }
            }
        }
        __syncthreads();
    }

    // ===== y ingest pipeline + conv epilogue -> Am =====
    auto y_issue = [&](int ys){
        const float* ybase = y + ((size_t)(b*128 + ys*32))*65536 + (size_t)h*256 + w0;
        #pragma unroll
        for (int p = 0; p < 8; p++){
            int idx = tid + p*128;            // 0..1023
            int cc = idx >> 5, t = idx & 31;  // 32 c-rows x 32 16B-units
            cp16(YSTU + cc*512 + t*16, ybase + (size_t)cc*65536 + t*4, 16);
        }
    };

    y_issue(0);
    cp_commit();

    // conv epilogue: acc (+conv bias) -> Am chunks 0..3 (overlaps y load 0)
    {
        float bv0[8], bv1[8];
        #pragma unroll
        for (int ni = 0; ni < 8; ni++){
            int n = wn*64 + ni*8 + lc*2;
            bv0[ni] = convb[n];
            bv1[ni] = convb[n+1];
        }
        #pragma unroll
        for (int mi = 0; mi < 4; mi++){
            int r0 = wm*64 + mi*16 + lr;
            int r1 = r0 + 8;
            int sw0 = (r0 & 1) << 5, sw1 = (r1 & 1) << 5;
            #pragma unroll
            for (int ni = 0; ni < 8; ni++){
                int n = wn*64 + ni*8 + lc*2;
                int ch = n >> 5;
                int sl = 2*lam32(n & 31);
                *(__half2*)(Am + ch*8192 + r0*64 + (sl ^ sw0)) =
                    __floats2half2_rn(acc[mi][ni][0] + bv0[ni], acc[mi][ni][1] + bv1[ni]);
                *(__half2*)(Am + ch*8192 + r1*64 + (sl ^ sw1)) =
                    __floats2half2_rn(acc[mi][ni][2] + bv0[ni], acc[mi][ni][3] + bv1[ni]);
            }
        }
    }

    #pragma unroll
    for (int ys = 0; ys < 4; ys++){
        cp_wait0();
        __syncthreads();
        int ch = 4 + ys;
        // convert YST fp32 -> Am chunk ch (interleaved half, row-swizzled)
        #pragma unroll
        for (int p = 0; p < 16; p++){
            int idx = tid + p*128;            // 0..2047
            int row = idx & 127, cp = idx >> 7;   // cp = channel pair 0..15
            float f0 = *(const float*)(YST + (2*cp    )*512 + row*4);
            float f1 = *(const float*)(YST + (2*cp + 1)*512 + row*4);
            int sl = 2*lam32(2*cp);
            *(__half2*)(Am + ch*8192 + row*64 + (sl ^ ((row & 1) << 5))) =
                __floats2half2_rn(f0, f1);
        }
        __syncthreads();
        if (ys < 3){ y_issue(ys+1); cp_commit(); }
    }

    // ===== mlp1: h1 = relu(A @ w1h + bias1), A resident, B double-buffered =====
    #pragma unroll
    for (int mi = 0; mi < 4; mi++)
        #pragma unroll
        for (int ni = 0; ni < 8; ni++)
            #pragma unroll
            for (int r = 0; r < 4; r++) acc[mi][ni][r] = 0.f;

    auto fillB = [&](int chunk, int s){
        #pragma unroll
        for (int p = 0; p < 4; p++){
            int idx = tid + p*128;
            int row = idx >> 2, t = idx & 3;
            cp16(BmU[s] + row*64 + (16*t ^ ((row & 1) << 5)),
                 g_w1h + (row*256 + chunk*32) + t*8, 16);
        }
    };

    fillB(0, 0);
    cp_commit();

    for (int chunk = 0; chunk < 8; chunk++){
        int s = chunk & 1;
        if (chunk + 1 < 8){ fillB(chunk+1, s^1); cp_commit(); cp_wait1(); }
        else cp_wait0();
        __syncthreads();

        char* Ac = Am + chunk*8192;
        uint4 bf[8];
        #pragma unroll
        for (int ni = 0; ni < 8; ni++){
            int brow = wn*64 + ni*8 + lr;
            bf[ni] = *(const uint4*)(Bm[s] + brow*64 + (16*lc ^ ((brow & 1) << 5)));
        }
        #pragma unroll
        for (int mi = 0; mi < 4; mi++){
            int ar0 = wm*64 + mi*16 + lr;
            int ar1 = ar0 + 8;
            uint4 A1 = *(const uint4*)(Ac + ar0*64 + (16*lc ^ ((ar0 & 1) << 5)));
            uint4 A2 = *(const uint4*)(Ac + ar1*64 + (16*lc ^ ((ar1 & 1) << 5)));
            #pragma unroll
            for (int ni = 0; ni < 8; ni++){
                mma_fp16(acc[mi][ni], A1.x, A2.x, A1.y, A2.y, bf[ni].x, bf[ni].y);
                mma_fp16(acc[mi][ni], A1.z, A2.z, A1.w, A2.w, bf[ni].z, bf[ni].w);
            }
        }
        __syncthreads();
    }

    // epilogue: per-batch bias + relu -> h1 fp32 + LN partial sums
    {
        float bv0[8], bv1[8];
        #pragma unroll
        for (int ni = 0; ni < 8; ni++){
            int n = wn*64 + ni*8 + lc*2;
            bv0[ni] = g_bias1[b*128 + n];
            bv1[ni] = g_bias1[b*128 + n + 1];
        }
        float ts = 0.f, ts2 = 0.f;
        #pragma unroll
        for (int mi = 0; mi < 4; mi++){
            int mr = m0 + wm*64 + mi*16 + lr;
            float* dst0 = g_h1 + (size_t)mr*128;
            float* dst1 = g_h1 + (size_t)(mr + 8)*128;
            #pragma unroll
            for (int ni = 0; ni < 8; ni++){
                int n = wn*64 + ni*8 + lc*2;
                float v0 = fmaxf(acc[mi][ni][0] + bv0[ni], 0.f);
                float v1 = fmaxf(acc[mi][ni][1] + bv1[ni], 0.f);
                float v2 = fmaxf(acc[mi][ni][2] + bv0[ni], 0.f);
                float v3 = fmaxf(acc[mi][ni][3] + bv1[ni], 0.f);
                *(float2*)(dst0 + n) = make_float2(v0, v1);
                *(float2*)(dst1 + n) = make_float2(v2, v3);
                ts  += v0 + v1 + v2 + v3;
                ts2 += v0*v0 + v1*v1 + v2*v2 + v3*v3;
            }
        }
        shs[tid] = ts; shs2[tid] = ts2;
        __syncthreads();
        for (int st = 64; st > 0; st >>= 1){
            if (tid < st){ shs[tid] += shs[tid+st]; shs2[tid] += shs2[tid+st]; }
            __syncthreads();
        }
        if (tid == 0){
            int cta = (m0 >> 7) & 511;
            g_part[(b*512 + cta)*2    ] = shs[0];
            g_part[(b*512 + cta)*2 + 1] = shs2[0];
        }
    }
}

// ---------------- layernorm finish ----------------
__global__ void ln_finish(){
    int b = blockIdx.x, tid = threadIdx.x;
    float s = 0.f, s2 = 0.f;
    for (int i = tid; i < 512; i += 256){
        s  += g_part[(b*512 + i)*2];
        s2 += g_part[(b*512 + i)*2 + 1];
    }
    __shared__ float sh[256], sh2[256];
    sh[tid] = s; sh2[tid] = s2; __syncthreads();
    for (int st = 128; st > 0; st >>= 1){
        if (tid < st){ sh[tid] += sh[tid+st]; sh2[tid] += sh2[tid+st]; }
        __syncthreads();
    }
    if (tid == 0){
        const float invN = 1.f / 8388608.f;
        float mu  = sh[0] * invN;
        float var = sh2[0] * invN - mu*mu;
        g_stats[b*2]     = mu;
        g_stats[b*2 + 1] = rsqrtf(var + 1e-5f);
    }
}

// ---------------- ln apply -> half interleaved ----------------
__global__ void ln_apply(){
    size_t e = ((size_t)blockIdx.x*256 + threadIdx.x)*4;
    int b = (int)(e >> 23);
    float mu = g_stats[b*2], rs = g_stats[b*2 + 1];
    size_t li = e & 8388607u;
    int m = (int)(e >> 7);
    int c = (int)(e & 127);
    float4 h = *(const float4*)&g_h1[e];
    float2 wf0 = __half22float2(*(const __half2*)(g_lnwh + li));
    float2 wf1 = __half22float2(*(const __half2*)(g_lnwh + li + 2));
    float2 bf0 = __half22float2(*(const __half2*)(g_lnbh + li));
    float2 bf1 = __half22float2(*(const __half2*)(g_lnbh + li + 2));
    float o0 = (h.x - mu)*rs*wf0.x + bf0.x;
    float o1 = (h.y - mu)*rs*wf0.y + bf0.y;
    float o2 = (h.z - mu)*rs*wf1.x + bf1.x;
    float o3 = (h.w - mu)*rs*wf1.y + bf1.y;
    __half* dst = g_lnh + (size_t)m*128;
    int s0 = (c >> 5)*32 + lam32(c & 31);
    int s1 = ((c+2) >> 5)*32 + lam32((c+2) & 31);
    *(__half2*)(dst + s0) = __floats2half2_rn(o0, o1);
    *(__half2*)(dst + s1) = __floats2half2_rn(o2, o3);
}

// ---------------- fused backend: GEMM(w3comb) -> T3 smem -> GEMM(w4comb) + identity ----------------
// dynamic smem: As @0 (8192), Bs @8192 (8192), T3 @16384 (32768) = 49152
#define CHAIN_SMEM 49152

__global__ __launch_bounds__(128, 2) void chain_fused_kernel(float* __restrict__ outf){
    extern __shared__ char dsm[];
    char* As = dsm;
    char* Bs = dsm + 8192;
    char* T3 = dsm + 16384;

    int m0  = blockIdx.x*128;
    int b   = m0 >> 16;
    int tid = threadIdx.x;
    int wid = tid >> 5, lane = tid & 31;
    int wm = wid & 1, wn = wid >> 1;
    int lr = lane >> 2, lc = lane & 3;

    float acc[4][8][4];
    #pragma unroll
    for (int mi = 0; mi < 4; mi++)
        #pragma unroll
        for (int ni = 0; ni < 8; ni++)
            #pragma unroll
            for (int r = 0; r < 4; r++) acc[mi][ni][r] = 0.f;

    // ---- phase 1: t3 = relu(lnh @ w3comb + bias3c) -> T3 smem ----
    #pragma unroll
    for (int chunk = 0; chunk < 4; chunk++){
        if (chunk) __syncthreads();
        #pragma unroll
        for (int p = 0; p < 4; p++){
            int idx = tid + p*128;
            int row = idx >> 2, t = idx & 3;
            uint32_t sw = 16*t ^ ((row & 1) << 5);
            uint4 va = *(const uint4*)(g_lnh + ((size_t)(m0 + row)*128 + chunk*32) + t*8);
            *(uint4*)(As + row*64 + sw) = va;
            uint4 vb = *(const uint4*)(g_w3comb + (row*128 + chunk*32) + t*8);
            *(uint4*)(Bs + row*64 + sw) = vb;
        }
        __syncthreads();

        uint4 bf[8];
        #pragma unroll
        for (int ni = 0; ni < 8; ni++){
            int brow = wn*64 + ni*8 + lr;
            bf[ni] = *(const uint4*)(Bs + brow*64 + (16*lc ^ ((brow & 1) << 5)));
        }
        #pragma unroll
        for (int mi = 0; mi < 4; mi++){
            int ar0 = wm*64 + mi*16 + lr;
            int ar1 = ar0 + 8;
            uint4 A1 = *(const uint4*)(As + ar0*64 + (16*lc ^ ((ar0 & 1) << 5)));
            uint4 A2 = *(const uint4*)(As + ar1*64 + (16*lc ^ ((ar1 & 1) << 5)));
            #pragma unroll
            for (int ni = 0; ni < 8; ni++){
                mma_fp16(acc[mi][ni], A1.x, A2.x, A1.y, A2.y, bf[ni].x, bf[ni].y);
                mma_fp16(acc[mi][ni], A1.z, A2.z, A1.w, A2.w, bf[ni].z, bf[ni].w);
            }
        }
    }

    // epilogue 1: bias3c + relu -> T3 (chunk-major interleaved, row-swizzled)
    {
        const float* bp = g_bias3c + b*128;
        #pragma unroll
        for (int mi = 0; mi < 4; mi++){
            int r0 = wm*64 + mi*16 + lr;
            int r1 = r0 + 8;
            int sw0 = (r0 & 1) << 5, sw1 = (r1 & 1) << 5;
            #pragma unroll
            for (int ni = 0; ni < 8; ni++){
                int n = wn*64 + ni*8 + lc*2;
                float b0 = bp[n], b1 = bp[n+1];
                int ch = n >> 5;
                int sl = 2*lam32(n & 31);
                *(__half2*)(T3 + ch*8192 + r0*64 + (sl ^ sw0)) =
                    __floats2half2_rn(fmaxf(acc[mi][ni][0] + b0, 0.f),
                                      fmaxf(acc[mi][ni][1] + b1, 0.f));
                *(__half2*)(T3 + ch*8192 + r1*64 + (sl ^ sw1)) =
                    __floats2half2_rn(fmaxf(acc[mi][ni][2] + b0, 0.f),
                                      fmaxf(acc[mi][ni][3] + b1, 0.f));
            }
        }
    }
    __syncthreads();

    // ---- phase 2: out = relu(t3 @ w4comb + bias4c) + h1, NCHW scatter ----
    #pragma unroll
    for (int mi = 0; mi < 4; mi++)
        #pragma unroll
        for (int ni = 0; ni < 8; ni++)
            #pragma unroll
            for (int r = 0; r < 4; r++) acc[mi][ni][r] = 0.f;

    #pragma unroll
    for (int chunk = 0; chunk < 4; chunk++){
        if (chunk) __syncthreads();
        #pragma unroll
        for (int p = 0; p < 4; p++){
            int idx = tid + p*128;
            int row = idx >> 2, t = idx & 3;
            uint4 vb = *(const uint4*)(g_w4comb + (row*128 + chunk*32) + t*8);
            *(uint4*)(Bs + row*64 + (16*t ^ ((row & 1) << 5))) = vb;
        }
        __syncthreads();

        uint4 bf[8];
        #pragma unroll
        for (int ni = 0; ni < 8; ni++){
            int brow = wn*64 + ni*8 + lr;
            bf[ni] = *(const uint4*)(Bs + brow*64 + (16*lc ^ ((brow & 1) << 5)));
        }
        char* Tc = T3 + chunk*8192;
        #pragma unroll
        for (int mi = 0; mi < 4; mi++){
            int ar0 = wm*64 + mi*16 + lr;
            int ar1 = ar0 + 8;
            uint4 A1 = *(const uint4*)(Tc + ar0*64 + (16*lc ^ ((ar0 & 1) << 5)));
            uint4 A2 = *(const uint4*)(Tc + ar1*64 + (16*lc ^ ((ar1 & 1) << 5)));
            #pragma unroll
            for (int ni = 0; ni < 8; ni++){
                mma_fp16(acc[mi][ni], A1.x, A2.x, A1.y, A2.y, bf[ni].x, bf[ni].y);
                mma_fp16(acc[mi][ni], A1.z, A2.z, A1.w, A2.w, bf[ni].z, bf[ni].w);
            }
        }
    }

    // epilogue 2: bias4c + relu + identity(h1) + NCHW scatter
    {
        const float* bp = g_bias4c + b*128;
        float bv0[8], bv1[8];
        #pragma unroll
        for (int ni = 0; ni < 8; ni++){
            int n = wn*64 + ni*8 + lc*2;
            bv0[ni] = bp[n];
            bv1[ni] = bp[n+1];
        }
        #pragma unroll
        for (int mi = 0; mi < 4; mi++){
            int mr = m0 + wm*64 + mi*16 + lr;
            int hw0 = mr & 65535, hw1 = (mr + 8) & 65535;
            const float* id0 = g_h1 + (size_t)mr*128;
            const float* id1 = g_h1 + (size_t)(mr + 8)*128;
            #pragma unroll
            for (int ni = 0; ni < 8; ni++){
                int n = wn*64 + ni*8 + lc*2;
                float* o0 = outf + ((size_t)(b*128 + n))*65536;
                float* o1 = outf + ((size_t)(b*128 + n + 1))*65536;
                o0[hw0] = fmaxf(acc[mi][ni][0] + bv0[ni], 0.f) + id0[n];
                o1[hw0] = fmaxf(acc[mi][ni][1] + bv1[ni], 0.f) + id0[n+1];
                o0[hw1] = fmaxf(acc[mi][ni][2] + bv0[ni], 0.f) + id1[n];
                o1[hw1] = fmaxf(acc[mi][ni][3] + bv1[ni], 0.f) + id1[n+1];
            }
        }
    }
}

// ---------------- launch ----------------
extern "C" void kernel_launch(void* const* d_in, const int* in_sizes, int n_in,
                              void* d_out, int out_size){
    const float* x      = (const float*)d_in[0];
    const float* y      = (const float*)d_in[1];
    const float* s      = (const float*)d_in[2];
    const float* conv_w = (const float*)d_in[4];
    const float* conv_b = (const float*)d_in[5];
    const float* mlp1_w = (const float*)d_in[6];
    const float* mlp1_b = (const float*)d_in[7];
    const float* ln_w   = (const float*)d_in[8];
    const float* ln_b   = (const float*)d_in[9];
    const float* m3_w1  = (const float*)d_in[10];
    const float* m3_b1  = (const float*)d_in[11];
    const float* m3_w2  = (const float*)d_in[12];
    const float* m3_b2  = (const float*)d_in[13];
    const float* m3_w3  = (const float*)d_in[14];
    const float* m3_b3  = (const float*)d_in[15];
    const float* m4_w1  = (const float*)d_in[16];
    const float* m4_b1  = (const float*)d_in[17];
    const float* m4_w2  = (const float*)d_in[18];
    const float* m4_b2  = (const float*)d_in[19];
    const float* m4_w3  = (const float*)d_in[20];
    const float* m4_b3  = (const float*)d_in[21];
    float* out = (float*)d_out;

    cudaFuncSetAttribute(conv_mlp1_kernel,
                         cudaFuncAttributeMaxDynamicSharedMemorySize, CM_SMEM);
    cudaFuncSetAttribute(chain_fused_kernel,
                         cudaFuncAttributeMaxDynamicSharedMemorySize, CHAIN_SMEM);

    void *pw3c, *pw4c, *pb3c, *pb4c;
    cudaGetSymbolAddress(&pw3c, g_w3comb);
    cudaGetSymbolAddress(&pw4c, g_w4comb);
    cudaGetSymbolAddress(&pb3c, g_bias3c);
    cudaGetSymbolAddress(&pb4c, g_bias4c);

    prep_w9h<<<1152, 256>>>(conv_w);
    prep_w1h<<<128, 256>>>(mlp1_w);
    combine_w12<<<32, 256>>>(m3_w1, m3_w2);
    combine_w3<<<64, 256>>>(m3_w3, (__half*)pw3c);
    combine_w12<<<32, 256>>>(m4_w1, m4_w2);
    combine_w3<<<64, 256>>>(m4_w3, (__half*)pw4c);
    combine_bias<<<1, 128>>>(s, m3_w1, m3_b1, m3_w2, m3_b2, m3_w3, m3_b3, (float*)pb3c);
    combine_bias<<<1, 128>>>(s, m4_w1, m4_b1, m4_w2, m4_b2, m4_w3, m4_b3, (float*)pb4c);
    prep_bias1<<<1, 128>>>(s, mlp1_w, mlp1_b);
    prep_lnh<<<8192, 256>>>(ln_w, ln_b);

    upsample_fused_kernel<<<dim3(128, 8, 8), 256>>>(x);
    conv_mlp1_kernel<<<4096, 128, CM_SMEM>>>(conv_b, y);   // conv + y ingest + mlp1 + LN partials

    ln_finish<<<8, 256>>>();
    ln_apply<<<65536, 256>>>();
    chain_fused_kernel<<<4096, 128, CHAIN_SMEM>>>(out);
}

// round 13
// speedup vs baseline: 1.0204x; 1.0204x over previous
#include <cuda_runtime.h>
#include <cuda_fp16.h>
#include <math.h>
#include <stdint.h>

#define BATCH 8
#define UPC   256
#define HH    256
#define WWD   256
#define HWN   65536
#define MTOT  (BATCH*HWN)   // 524288

// ---------------- scratch (static device globals; allocation-free) ----------------
__device__ __half g_xuPh[(size_t)BATCH*HWN*UPC];   // [b][h][c8][w][32] pair-interleaved half
__device__ __half g_fh  [(size_t)MTOT*256];        // y-half lives in channels 128..255
__device__ __half g_h1h[(size_t)MTOT*128];         // mlp1 out HALF (LN input + identity)
__device__ __half g_lnh[(size_t)MTOT*128];         // layernorm out, interleaved half
__device__ __half g_t3h[(size_t)MTOT*128];         // collapsed-mlp3 out
__device__ __half g_w9ph[9*8*128*32];              // conv weights [off][c8][co][32] interleaved
__device__ __half g_w1h [128*256];                 // mlp1 W^T [n][k-interleaved]
__device__ __half g_w3comb[128*128];
__device__ __half g_w4comb[128*128];
__device__ float  g_wtmp3[128*64];
__device__ float  g_wtmp4[128*64];
__device__ __half g_lnwh[(size_t)HWN*128];
__device__ __half g_lnbh[(size_t)HWN*128];
__device__ float  g_bias1[BATCH*128];
__device__ float  g_bias3c[BATCH*128];
__device__ float  g_bias4c[BATCH*128];
__device__ float  g_part[BATCH*512*2];
__device__ float  g_stats[BATCH*2];

// channel c (0..31) -> half slot within 32-half chunk (pair-interleaved)
__device__ __forceinline__ int lam32(int c){
    int g  = c >> 4;
    int kp = (c & 15) >> 1;
    int o  = c & 1;
    return 8*(kp & 3) + 4*g + 2*(kp >> 2) + o;
}

__device__ __forceinline__ void mma_fp16(float c[4],
        uint32_t a0, uint32_t a1, uint32_t a2, uint32_t a3,
        uint32_t b0, uint32_t b1){
    asm volatile(
        "mma.sync.aligned.m16n8k16.row.col.f32.f16.f16.f32 "
        "{%0,%1,%2,%3}, {%4,%5,%6,%7}, {%8,%9}, {%0,%1,%2,%3};"
        : "+f"(c[0]), "+f"(c[1]), "+f"(c[2]), "+f"(c[3])
        : "r"(a0), "r"(a1), "r"(a2), "r"(a3), "r"(b0), "r"(b1));
}

__device__ __forceinline__ void cp16(uint32_t dst, const void* src, int bytes){
    asm volatile("cp.async.cg.shared.global [%0], [%1], 16, %2;"
                 :: "r"(dst), "l"(src), "r"(bytes));
}
__device__ __forceinline__ void cp_commit(){ asm volatile("cp.async.commit_group;"); }
__device__ __forceinline__ void cp_wait1(){ asm volatile("cp.async.wait_group 1;"); }
__device__ __forceinline__ void cp_wait0(){ asm volatile("cp.async.wait_group 0;"); }

// ---------------- merged prep kernel 1 (everything independent) ----------------
// blocks: [0,1152) w9h | [1152,1280) w1h | [1280,1312) w12(m3) | [1312,1344) w12(m4)
//         1344 bias3c | 1345 bias4c | 1346 bias1 | [1347,1347+8192) lnh
__global__ void prep_all1(const float* __restrict__ cw,
                          const float* __restrict__ m1w, const float* __restrict__ m1b,
                          const float* __restrict__ sv,
                          const float* __restrict__ w31, const float* __restrict__ b31,
                          const float* __restrict__ w32, const float* __restrict__ b32,
                          const float* __restrict__ w33, const float* __restrict__ b33,
                          const float* __restrict__ w41, const float* __restrict__ b41,
                          const float* __restrict__ w42, const float* __restrict__ b42,
                          const float* __restrict__ w43, const float* __restrict__ b43,
                          const float* __restrict__ lnw, const float* __restrict__ lnb){
    int blk = blockIdx.x;
    int tid = threadIdx.x;

    if (blk < 1152){
        int i = blk*256 + tid;
        if (i < 9*8*128*32){
            int c   = i & 31;
            int co  = (i >> 5) & 127;
            int c8  = (i >> 12) & 7;
            int off = i >> 15;
            int ci  = c8*32 + c;
            g_w9ph[(((off*8 + c8)*128 + co)*32) + lam32(c)] =
                __float2half_rn(cw[(co*256 + ci)*9 + off]);
        }
    } else if (blk < 1280){
        int i = (blk - 1152)*256 + tid;
        int k = i & 255, n = i >> 8;
        g_w1h[n*256 + (k>>5)*32 + lam32(k & 31)] = __float2half_rn(m1w[k*128 + n]);
    } else if (blk < 1312){
        int i = (blk - 1280)*256 + tid;
        int k = i >> 6, j = i & 63;
        float s = 0.f;
        #pragma unroll 8
        for (int t = 0; t < 64; t++) s += w31[k*64 + t]*w32[t*64 + j];
        g_wtmp3[k*64 + j] = s;
    } else if (blk < 1344){
        int i = (blk - 1312)*256 + tid;
        int k = i >> 6, j = i & 63;
        float s = 0.f;
        #pragma unroll 8
        for (int t = 0; t < 64; t++) s += w41[k*64 + t]*w42[t*64 + j];
        g_wtmp4[k*64 + j] = s;
    } else if (blk < 1346){
        // combine_bias for m3 (blk 1344) / m4 (blk 1345)
        const float* w1 = (blk == 1344) ? w31 : w41;
        const float* b1 = (blk == 1344) ? b31 : b41;
        const float* w2 = (blk == 1344) ? w32 : w42;
        const float* b2 = (blk == 1344) ? b32 : b42;
        const float* w3 = (blk == 1344) ? w33 : w43;
        const float* b3 = (blk == 1344) ? b33 : b43;
        float* ob = (blk == 1344) ? g_bias3c : g_bias4c;
        __shared__ float v[64], u[64];
        int t = tid;
        for (int b = 0; b < BATCH; b++){
            float sb = sv[b];
            if (t < 64) v[t] = b1[t] + sb*w1[128*64 + t];
            __syncthreads();
            if (t < 64){
                float s = b2[t];
                #pragma unroll 8
                for (int i = 0; i < 64; i++) s += v[i]*w2[i*64 + t];
                u[t] = s;
            }
            __syncthreads();
            if (t < 128){
                float s = b3[t];
                #pragma unroll 8
                for (int j = 0; j < 64; j++) s += u[j]*w3[j*128 + t];
                ob[b*128 + t] = s;
            }
            __syncthreads();
        }
    } else if (blk == 1346){
        if (tid < 128)
            for (int b = 0; b < BATCH; b++)
                g_bias1[b*128+tid] = m1b[tid] + sv[b]*m1w[256*128 + tid];
    } else {
        size_t e = ((size_t)(blk - 1347)*256 + tid)*4;
        float4 w = *(const float4*)&lnw[e];
        float4 b = *(const float4*)&lnb[e];
        *(__half2*)(g_lnwh + e)     = __floats2half2_rn(w.x, w.y);
        *(__half2*)(g_lnwh + e + 2) = __floats2half2_rn(w.z, w.w);
        *(__half2*)(g_lnbh + e)     = __floats2half2_rn(b.x, b.y);
        *(__half2*)(g_lnbh + e + 2) = __floats2half2_rn(b.z, b.w);
    }
}

// ---------------- merged prep kernel 2 (combine_w3, depends on wtmp) ----------------
__global__ void prep_all2(const float* __restrict__ w33, const float* __restrict__ w43){
    int blk = blockIdx.x;
    int i = (blk & 63)*256 + threadIdx.x;
    int k = i >> 7, n = i & 127;
    const float* wt = (blk < 64) ? g_wtmp3 : g_wtmp4;
    const float* w3 = (blk < 64) ? w33 : w43;
    __half* o = (blk < 64) ? g_w3comb : g_w4comb;
    float s = 0.f;
    #pragma unroll 8
    for (int j = 0; j < 64; j++) s += wt[k*64 + j]*w3[j*128 + n];
    o[n*128 + (k>>5)*32 + lam32(k & 31)] = __float2half_rn(s);
}

// ---------------- fused bicubic 2x upsample -> interleaved half (g_xuPh) ----------------
__global__ __launch_bounds__(256) void upsample_fused_kernel(const float* __restrict__ x){
    __shared__ __half sm[2][256][32];
    int kh = blockIdx.x, c8 = blockIdx.y, b = blockIdx.z;
    int tid = threadIdx.x;
    int lane = tid & 31, warp = tid >> 5;

    int rr[5];
    #pragma unroll
    for (int i = 0; i < 5; i++){
        int r = kh - 2 + i; rr[i] = min(max(r,0),127);
    }
    const float we0=-0.03515625f, we1=0.26171875f, we2=0.87890625f, we3=-0.10546875f;
    const float wo0=-0.10546875f, wo1=0.87890625f, wo2=0.26171875f, wo3=-0.03515625f;

    #pragma unroll
    for (int q = 0; q < 4; q++){
        int cg = warp*4 + q;
        int c  = c8*32 + cg;
        const float* xp = x + ((size_t)(b*256 + c))*16384;
        int slot = lam32(cg);
        #pragma unroll
        for (int j = 0; j < 4; j++){
            int kw = lane + 32*j;
            int cc[5];
            #pragma unroll
            for (int i = 0; i < 5; i++){
                int cw_ = kw - 2 + i; cc[i] = min(max(cw_,0),127);
            }
            float he[5], ho[5];
            #pragma unroll
            for (int i = 0; i < 5; i++){
                const float* row = xp + rr[i]*128;
                float v0=row[cc[0]], v1=row[cc[1]], v2=row[cc[2]], v3=row[cc[3]], v4=row[cc[4]];
                he[i] = we0*v0 + we1*v1 + we2*v2 + we3*v3;
                ho[i] = wo0*v1 + wo1*v2 + wo2*v3 + wo3*v4;
            }
            float o00 = we0*he[0]+we1*he[1]+we2*he[2]+we3*he[3];
            float o01 = we0*ho[0]+we1*ho[1]+we2*ho[2]+we3*ho[3];
            float o10 = wo0*he[1]+wo1*he[2]+wo2*he[3]+wo3*he[4];
            float o11 = wo0*ho[1]+wo1*ho[2]+wo2*ho[3]+wo3*ho[4];
            sm[0][2*kw  ][slot] = __float2half_rn(o00);
            sm[0][2*kw+1][slot] = __float2half_rn(o01);
            sm[1][2*kw  ][slot] = __float2half_rn(o10);
            sm[1][2*kw+1][slot] = __float2half_rn(o11);
        }
    }
    __syncthreads();

    __half* out0 = g_xuPh + ((size_t)((b*256 + 2*kh    )*8 + c8))*8192;
    __half* out1 = g_xuPh + ((size_t)((b*256 + 2*kh + 1)*8 + c8))*8192;
    const uint4* s0 = (const uint4*)&sm[0][0][0];
    const uint4* s1 = (const uint4*)&sm[1][0][0];
    #pragma unroll
    for (int p = 0; p < 4; p++){
        ((uint4*)out0)[p*256 + tid] = s0[p*256 + tid];
        ((uint4*)out1)[p*256 + tid] = s1[p*256 + tid];
    }
}

// ---------------- y NCHW -> g_fh half (channels 128..255, interleaved slots) ----------------
__global__ void ycopy_kernel(const float* __restrict__ y){
    __shared__ float tile[32][33];
    int w0 = blockIdx.x*32, cb = blockIdx.y;
    int bh = blockIdx.z;
    int b = bh >> 8, h = bh & 255;
    int tx = threadIdx.x, ty = threadIdx.y;
    int c0 = cb*32;
    #pragma unroll
    for (int k = 0; k < 4; k++){
        int c = c0 + ty + k*8;
        tile[ty + k*8][tx] = y[(((size_t)b*128 + c)*256 + h)*256 + w0 + tx];
    }
    __syncthreads();
    int slot = (4 + cb)*32 + lam32(tx);
    #pragma unroll
    for (int k = 0; k < 4; k++){
        int w = w0 + ty + k*8;
        g_fh[(((size_t)b*256 + h)*256 + w)*256 + slot] = __float2half_rn(tile[tx][ty + k*8]);
    }
}

// ---------------- FUSED conv 3x3 + mlp1 (R11 structure, h1->half, B dbuf) ----------------
// SMEM plan (dynamic, 81920 B):
//   conv phase : Ab[2] @0/@8320, Bb[2] @16640/@41216
//   mlp1 phase : A-tile 8 chunks @0 (65536), B double buffer @65536/@73728
#define CM_SMEM 81920

__global__ __launch_bounds__(128, 2) void conv_mlp1_kernel(const float* __restrict__ convb){
    extern __shared__ char dsm[];
    __shared__ float shs[128], shs2[128];
    char* const Ab[2] = {dsm, dsm + 8320};
    char* const Bb[2] = {dsm + 16640, dsm + 41216};
    uint32_t Au[2], Bu[2];
    Au[0] = (uint32_t)__cvta_generic_to_shared(Ab[0]);
    Au[1] = (uint32_t)__cvta_generic_to_shared(Ab[1]);
    Bu[0] = (uint32_t)__cvta_generic_to_shared(Bb[0]);
    Bu[1] = (uint32_t)__cvta_generic_to_shared(Bb[1]);
    char* Am = dsm;                       // mlp1 A tile (8 chunks of 8192)
    uint32_t AmU = (uint32_t)__cvta_generic_to_shared(Am);
    char* const Bm[2] = {dsm + 65536, dsm + 73728};
    uint32_t BmU[2];
    BmU[0] = (uint32_t)__cvta_generic_to_shared(Bm[0]);
    BmU[1] = (uint32_t)__cvta_generic_to_shared(Bm[1]);

    int bx = blockIdx.x;
    int w0 = (bx & 1)*128;
    int h  = (bx >> 1) & 255;
    int b  = bx >> 9;
    int m0 = b*65536 + h*256 + w0;
    int tid = threadIdx.x;
    int wid = tid >> 5, lane = tid & 31;
    int wm = wid & 1, wn = wid >> 1;
    int lr = lane >> 2, lc = lane & 3;

    int hhs[3], off3s[3], nh = 0;
    #pragma unroll
    for (int dh = -1; dh <= 1; dh++){
        int hh = h + dh;
        if (hh >= 0 && hh < HH){ hhs[nh] = hh; off3s[nh] = (dh+1)*3; nh++; }
    }
    int nch = nh*8;

    float acc[4][8][4];
    #pragma unroll
    for (int mi = 0; mi < 4; mi++)
        #pragma unroll
        for (int ni = 0; ni < 8; ni++)
            #pragma unroll
            for (int r = 0; r < 4; r++) acc[mi][ni][r] = 0.f;

    auto fill = [&](int i, int s){
        int ih = i >> 3, c8 = i & 7;
        const __half* aplane = g_xuPh + ((size_t)((b*256 + hhs[ih])*8 + c8))*8192;
        #pragma unroll
        for (int p = 0; p < 5; p++){
            int idx = tid + p*128;
            if (idx < 520){
                int row = idx >> 2, t = idx & 3;
                int w_in = w0 - 1 + row;
                int ok = (w_in >= 0 && w_in < WWD) ? 16 : 0;
                int wc = min(max(w_in, 0), WWD-1);
                cp16(Au[s] + row*64 + (16*t ^ ((row & 1) << 5)),
                     aplane + wc*32 + t*8, ok);
            }
        }
        const __half* wb = g_w9ph + ((size_t)(off3s[ih]*8 + c8))*128*32;
        #pragma unroll
        for (int p = 0; p < 12; p++){
            int idx = tid + p*128;
            int row = idx >> 2, t = idx & 3;
            int dwi = row >> 7, co = row & 127;
            cp16(Bu[s] + row*64 + (16*t ^ ((row & 1) << 5)),
                 wb + ((size_t)dwi*8*128*32) + co*32 + t*8, 16);
        }
    };

    // ===== conv mainloop =====
    fill(0, 0);
    cp_commit();

    for (int i = 0; i < nch; i++){
        int s = i & 1;
        if (i + 1 < nch){ fill(i+1, s^1); cp_commit(); cp_wait1(); }
        else cp_wait0();
        __syncthreads();

        char* As = Ab[s];
        char* Bs = Bb[s];
        #pragma unroll
        for (int dwi = 0; dwi < 3; dwi++){
            uint4 bf[8];
            #pragma unroll
            for (int ni = 0; ni < 8; ni++){
                int brow = dwi*128 + wn*64 + ni*8 + lr;
                bf[ni] = *(const uint4*)(Bs + brow*64 + (16*lc ^ ((brow & 1) << 5)));
            }
            #pragma unroll
            for (int mi = 0; mi < 4; mi++){
                int ar0 = wm*64 + mi*16 + lr + dwi;
                int ar1 = ar0 + 8;
                uint4 A1 = *(const uint4*)(As + ar0*64 + (16*lc ^ ((ar0 & 1) << 5)));
                uint4 A2 = *(const uint4*)(As + ar1*64 + (16*lc ^ ((ar1 & 1) << 5)));
                #pragma unroll
                for (int ni = 0; ni < 8; ni++){
                    mma_fp16(acc[mi][ni], A1.x, A2.x, A1.y, A2.y, bf[ni].x, bf[ni].y);
                    mma_fp16(acc[mi][ni], A1.z, A2.z, A1.w, A2.w, bf[ni].z, bf[ni].w);
                }
            }
        }
        __syncthreads();
    }

    // ===== stage conv result as mlp1 A chunks 0..3; cp.async y-half to chunks 4..7 =====
    #pragma unroll
    for (int p = 0; p < 16; p++){
        int idx = tid + p*128;
        int ch  = 4 + (idx >> 9);
        int rem = idx & 511;
        int row = rem >> 2, t = rem & 3;
        cp16(AmU + ch*8192 + row*64 + (16*t ^ ((row & 1) << 5)),
             g_fh + ((size_t)(m0 + row)*256 + ch*32) + t*8, 16);
    }
    cp_commit();

    {
        float bv0[8], bv1[8];
        #pragma unroll
        for (int ni = 0; ni < 8; ni++){
            int n = wn*64 + ni*8 + lc*2;
            bv0[ni] = convb[n];
            bv1[ni] = convb[n+1];
        }
        #pragma unroll
        for (int mi = 0; mi < 4; mi++){
            int r0 = wm*64 + mi*16 + lr;
            int r1 = r0 + 8;
            int sw0 = (r0 & 1) << 5, sw1 = (r1 & 1) << 5;
            #pragma unroll
            for (int ni = 0; ni < 8; ni++){
                int n = wn*64 + ni*8 + lc*2;
                int ch = n >> 5;
                int sl = 2*lam32(n & 31);
                *(__half2*)(Am + ch*8192 + r0*64 + (sl ^ sw0)) =
                    __floats2half2_rn(acc[mi][ni][0] + bv0[ni], acc[mi][ni][1] + bv1[ni]);
                *(__half2*)(Am + ch*8192 + r1*64 + (sl ^ sw1)) =
                    __floats2half2_rn(acc[mi][ni][2] + bv0[ni], acc[mi][ni][3] + bv1[ni]);
            }
        }
    }
    cp_wait0();
    __syncthreads();

    // ===== mlp1: h1 = relu(A @ w1h + bias1), A resident, B double-buffered =====
    #pragma unroll
    for (int mi = 0; mi < 4; mi++)
        #pragma unroll
        for (int ni = 0; ni < 8; ni++)
            #pragma unroll
            for (int r = 0; r < 4; r++) acc[mi][ni][r] = 0.f;

    auto fillB = [&](int chunk, int s){
        #pragma unroll
        for (int p = 0; p < 4; p++){
            int idx = tid + p*128;
            int row = idx >> 2, t = idx & 3;
            cp16(BmU[s] + row*64 + (16*t ^ ((row & 1) << 5)),
                 g_w1h + (row*256 + chunk*32) + t*8, 16);
        }
    };

    fillB(0, 0);
    cp_commit();

    for (int chunk = 0; chunk < 8; chunk++){
        int s = chunk & 1;
        if (chunk + 1 < 8){ fillB(chunk+1, s^1); cp_commit(); cp_wait1(); }
        else cp_wait0();
        __syncthreads();

        char* Ac = Am + chunk*8192;
        uint4 bf[8];
        #pragma unroll
        for (int ni = 0; ni < 8; ni++){
            int brow = wn*64 + ni*8 + lr;
            bf[ni] = *(const uint4*)(Bm[s] + brow*64 + (16*lc ^ ((brow & 1) << 5)));
        }
        #pragma unroll
        for (int mi = 0; mi < 4; mi++){
            int ar0 = wm*64 + mi*16 + lr;
            int ar1 = ar0 + 8;
            uint4 A1 = *(const uint4*)(Ac + ar0*64 + (16*lc ^ ((ar0 & 1) << 5)));
            uint4 A2 = *(const uint4*)(Ac + ar1*64 + (16*lc ^ ((ar1 & 1) << 5)));
            #pragma unroll
            for (int ni = 0; ni < 8; ni++){
                mma_fp16(acc[mi][ni], A1.x, A2.x, A1.y, A2.y, bf[ni].x, bf[ni].y);
                mma_fp16(acc[mi][ni], A1.z, A2.z, A1.w, A2.w, bf[ni].z, bf[ni].w);
            }
        }
        __syncthreads();
    }

    // epilogue: per-batch bias + relu -> h1 HALF + LN partial sums (fp32)
    {
        float bv0[8], bv1[8];
        #pragma unroll
        for (int ni = 0; ni < 8; ni++){
            int n = wn*64 + ni*8 + lc*2;
            bv0[ni] = g_bias1[b*128 + n];
            bv1[ni] = g_bias1[b*128 + n + 1];
        }
        float ts = 0.f, ts2 = 0.f;
        #pragma unroll
        for (int mi = 0; mi < 4; mi++){
            int mr = m0 + wm*64 + mi*16 + lr;
            __half* dst0 = g_h1h + (size_t)mr*128;
            __half* dst1 = g_h1h + (size_t)(mr + 8)*128;
            #pragma unroll
            for (int ni = 0; ni < 8; ni++){
                int n = wn*64 + ni*8 + lc*2;
                float v0 = fmaxf(acc[mi][ni][0] + bv0[ni], 0.f);
                float v1 = fmaxf(acc[mi][ni][1] + bv1[ni], 0.f);
                float v2 = fmaxf(acc[mi][ni][2] + bv0[ni], 0.f);
                float v3 = fmaxf(acc[mi][ni][3] + bv1[ni], 0.f);
                *(__half2*)(dst0 + n) = __floats2half2_rn(v0, v1);
                *(__half2*)(dst1 + n) = __floats2half2_rn(v2, v3);
                ts  += v0 + v1 + v2 + v3;
                ts2 += v0*v0 + v1*v1 + v2*v2 + v3*v3;
            }
        }
        shs[tid] = ts; shs2[tid] = ts2;
        __syncthreads();
        for (int st = 64; st > 0; st >>= 1){
            if (tid < st){ shs[tid] += shs[tid+st]; shs2[tid] += shs2[tid+st]; }
            __syncthreads();
        }
        if (tid == 0){
            int cta = (m0 >> 7) & 511;
            g_part[(b*512 + cta)*2    ] = shs[0];
            g_part[(b*512 + cta)*2 + 1] = shs2[0];
        }
    }
}

// ---------------- layernorm finish ----------------
__global__ void ln_finish(){
    int b = blockIdx.x, tid = threadIdx.x;
    float s = 0.f, s2 = 0.f;
    for (int i = tid; i < 512; i += 256){
        s  += g_part[(b*512 + i)*2];
        s2 += g_part[(b*512 + i)*2 + 1];
    }
    __shared__ float sh[256], sh2[256];
    sh[tid] = s; sh2[tid] = s2; __syncthreads();
    for (int st = 128; st > 0; st >>= 1){
        if (tid < st){ sh[tid] += sh[tid+st]; sh2[tid] += sh2[tid+st]; }
        __syncthreads();
    }
    if (tid == 0){
        const float invN = 1.f / 8388608.f;
        float mu  = sh[0] * invN;
        float var = sh2[0] * invN - mu*mu;
        g_stats[b*2]     = mu;
        g_stats[b*2 + 1] = rsqrtf(var + 1e-5f);
    }
}

// ---------------- ln apply (h1 half in) -> half interleaved ----------------
__global__ void ln_apply(){
    size_t e = ((size_t)blockIdx.x*256 + threadIdx.x)*4;
    int b = (int)(e >> 23);
    float mu = g_stats[b*2], rs = g_stats[b*2 + 1];
    size_t li = e & 8388607u;
    int m = (int)(e >> 7);
    int c = (int)(e & 127);
    float2 h01 = __half22float2(*(const __half2*)(g_h1h + e));
    float2 h23 = __half22float2(*(const __half2*)(g_h1h + e + 2));
    float2 wf0 = __half22float2(*(const __half2*)(g_lnwh + li));
    float2 wf1 = __half22float2(*(const __half2*)(g_lnwh + li + 2));
    float2 bf0 = __half22float2(*(const __half2*)(g_lnbh + li));
    float2 bf1 = __half22float2(*(const __half2*)(g_lnbh + li + 2));
    float o0 = (h01.x - mu)*rs*wf0.x + bf0.x;
    float o1 = (h01.y - mu)*rs*wf0.y + bf0.y;
    float o2 = (h23.x - mu)*rs*wf1.x + bf1.x;
    float o3 = (h23.y - mu)*rs*wf1.y + bf1.y;
    __half* dst = g_lnh + (size_t)m*128;
    int s0 = (c >> 5)*32 + lam32(c & 31);
    int s1 = ((c+2) >> 5)*32 + lam32((c+2) & 31);
    *(__half2*)(dst + s0) = __floats2half2_rn(o0, o1);
    *(__half2*)(dst + s1) = __floats2half2_rn(o2, o3);
}

// ---------------- collapsed-chain fp16 GEMM (R9/R11 version): K=128, N=128 ----------------
template<int EPI>
__global__ __launch_bounds__(128, 2) void hgemm2_kernel(
    const __half* __restrict__ A, const __half* __restrict__ Bw,
    const float* __restrict__ biasPB,
    __half* __restrict__ outh, float* __restrict__ outf)
{
    __shared__ __align__(16) char As[128*64];
    __shared__ __align__(16) char Bs[128*64];

    int m0  = blockIdx.x*128;
    int tid = threadIdx.x;
    int wid = tid >> 5, lane = tid & 31;
    int wm = wid & 1, wn = wid >> 1;
    int lr = lane >> 2, lc = lane & 3;

    float acc[4][8][4];
    #pragma unroll
    for (int mi = 0; mi < 4; mi++)
        #pragma unroll
        for (int ni = 0; ni < 8; ni++)
            #pragma unroll
            for (int r = 0; r < 4; r++) acc[mi][ni][r] = 0.f;

    #pragma unroll
    for (int chunk = 0; chunk < 4; chunk++){
        if (chunk) __syncthreads();
        #pragma unroll
        for (int p = 0; p < 4; p++){
            int idx = tid + p*128;
            int row = idx >> 2, t = idx & 3;
            uint32_t sw = 16*t ^ ((row & 1) << 5);
            uint4 va = *(const uint4*)(A + ((size_t)(m0 + row)*128 + chunk*32) + t*8);
            *(uint4*)(As + row*64 + sw) = va;
            uint4 vb = *(const uint4*)(Bw + ((size_t)row*128 + chunk*32) + t*8);
            *(uint4*)(Bs + row*64 + sw) = vb;
        }
        __syncthreads();

        uint4 bf[8];
        #pragma unroll
        for (int ni = 0; ni < 8; ni++){
            int brow = wn*64 + ni*8 + lr;
            bf[ni] = *(const uint4*)(Bs + brow*64 + (16*lc ^ ((brow & 1) << 5)));
        }
        #pragma unroll
        for (int mi = 0; mi < 4; mi++){
            int ar0 = wm*64 + mi*16 + lr;
            int ar1 = ar0 + 8;
            uint4 A1 = *(const uint4*)(As + ar0*64 + (16*lc ^ ((ar0 & 1) << 5)));
            uint4 A2 = *(const uint4*)(As + ar1*64 + (16*lc ^ ((ar1 & 1) << 5)));
            #pragma unroll
            for (int ni = 0; ni < 8; ni++){
                mma_fp16(acc[mi][ni], A1.x, A2.x, A1.y, A2.y, bf[ni].x, bf[ni].y);
                mma_fp16(acc[mi][ni], A1.z, A2.z, A1.w, A2.w, bf[ni].z, bf[ni].w);
            }
        }
    }

    int b = m0 >> 16;
    const float* bp = biasPB + b*128;
    float bv0[8], bv1[8];
    int slot[8];
    #pragma unroll
    for (int ni = 0; ni < 8; ni++){
        int n = wn*64 + ni*8 + lc*2;
        bv0[ni] = bp[n];
        bv1[ni] = bp[n+1];
        slot[ni] = (n >> 5)*32 + lam32(n & 31);
    }

    #pragma unroll
    for (int mi = 0; mi < 4; mi++){
        int mr = m0 + wm*64 + mi*16 + lr;
        if constexpr (EPI == 1){
            int hw0 = mr & 65535, hw1 = (mr + 8) & 65535;
            const __half* id0 = g_h1h + (size_t)mr*128;
            const __half* id1 = g_h1h + (size_t)(mr + 8)*128;
            #pragma unroll
            for (int ni = 0; ni < 8; ni++){
                int n = wn*64 + ni*8 + lc*2;
                float2 i0 = __half22float2(*(const __half2*)(id0 + n));
                float2 i1 = __half22float2(*(const __half2*)(id1 + n));
                float* o0 = outf + ((size_t)(b*128 + n))*65536;
                float* o1 = outf + ((size_t)(b*128 + n + 1))*65536;
                o0[hw0] = fmaxf(acc[mi][ni][0] + bv0[ni], 0.f) + i0.x;
                o1[hw0] = fmaxf(acc[mi][ni][1] + bv1[ni], 0.f) + i0.y;
                o0[hw1] = fmaxf(acc[mi][ni][2] + bv0[ni], 0.f) + i1.x;
                o1[hw1] = fmaxf(acc[mi][ni][3] + bv1[ni], 0.f) + i1.y;
            }
        } else {
            __half* dst0 = outh + (size_t)mr*128;
            __half* dst1 = outh + (size_t)(mr + 8)*128;
            #pragma unroll
            for (int ni = 0; ni < 8; ni++){
                *(__half2*)(dst0 + slot[ni]) =
                    __floats2half2_rn(fmaxf(acc[mi][ni][0] + bv0[ni], 0.f),
                                      fmaxf(acc[mi][ni][1] + bv1[ni], 0.f));
                *(__half2*)(dst1 + slot[ni]) =
                    __floats2half2_rn(fmaxf(acc[mi][ni][2] + bv0[ni], 0.f),
                                      fmaxf(acc[mi][ni][3] + bv1[ni], 0.f));
            }
        }
    }
}

// ---------------- launch ----------------
extern "C" void kernel_launch(void* const* d_in, const int* in_sizes, int n_in,
                              void* d_out, int out_size){
    const float* x      = (const float*)d_in[0];
    const float* y      = (const float*)d_in[1];
    const float* s      = (const float*)d_in[2];
    const float* conv_w = (const float*)d_in[4];
    const float* conv_b = (const float*)d_in[5];
    const float* mlp1_w = (const float*)d_in[6];
    const float* mlp1_b = (const float*)d_in[7];
    const float* ln_w   = (const float*)d_in[8];
    const float* ln_b   = (const float*)d_in[9];
    const float* m3_w1  = (const float*)d_in[10];
    const float* m3_b1  = (const float*)d_in[11];
    const float* m3_w2  = (const float*)d_in[12];
    const float* m3_b2  = (const float*)d_in[13];
    const float* m3_w3  = (const float*)d_in[14];
    const float* m3_b3  = (const float*)d_in[15];
    const float* m4_w1  = (const float*)d_in[16];
    const float* m4_b1  = (const float*)d_in[17];
    const float* m4_w2  = (const float*)d_in[18];
    const float* m4_b2  = (const float*)d_in[19];
    const float* m4_w3  = (const float*)d_in[20];
    const float* m4_b3  = (const float*)d_in[21];
    float* out = (float*)d_out;

    cudaFuncSetAttribute(conv_mlp1_kernel,
                         cudaFuncAttributeMaxDynamicSharedMemorySize, CM_SMEM);

    void *plnh, *pt3, *pw3c, *pw4c, *pb3c, *pb4c;
    cudaGetSymbolAddress(&plnh, g_lnh);
    cudaGetSymbolAddress(&pt3, g_t3h);
    cudaGetSymbolAddress(&pw3c, g_w3comb);
    cudaGetSymbolAddress(&pw4c, g_w4comb);
    cudaGetSymbolAddress(&pb3c, g_bias3c);
    cudaGetSymbolAddress(&pb4c, g_bias4c);

    prep_all1<<<9539, 256>>>(conv_w, mlp1_w, mlp1_b, s,
                             m3_w1, m3_b1, m3_w2, m3_b2, m3_w3, m3_b3,
                             m4_w1, m4_b1, m4_w2, m4_b2, m4_w3, m4_b3,
                             ln_w, ln_b);
    prep_all2<<<128, 256>>>(m3_w3, m4_w3);

    upsample_fused_kernel<<<dim3(128, 8, 8), 256>>>(x);
    ycopy_kernel<<<dim3(8, 4, 2048), dim3(32, 8)>>>(y);
    conv_mlp1_kernel<<<4096, 128, CM_SMEM>>>(conv_b);

    ln_finish<<<8, 256>>>();
    ln_apply<<<65536, 256>>>();

    hgemm2_kernel<0><<<4096, 128>>>((const __half*)plnh, (const __half*)pw3c,
                                    (const float*)pb3c, (__half*)pt3, nullptr);
    hgemm2_kernel<1><<<4096, 128>>>((const __half*)pt3, (const __half*)pw4c,
                                    (const float*)pb4c, nullptr, out);
}

// round 14
// speedup vs baseline: 1.0365x; 1.0158x over previous
#include <cuda_runtime.h>
#include <cuda_fp16.h>
#include <math.h>
#include <stdint.h>

#define BATCH 8
#define UPC   256
#define HH    256
#define WWD   256
#define HWN   65536
#define MTOT  (BATCH*HWN)   // 524288

// ---------------- scratch (static device globals; allocation-free) ----------------
__device__ __half g_xuPh[(size_t)BATCH*HWN*UPC];   // [b][h][c8][w][32] pair-interleaved half
__device__ __half g_fh  [(size_t)MTOT*256];        // y-half lives in channels 128..255
__device__ float  g_h1 [(size_t)MTOT*128];         // mlp1 out fp32 (LN stats + identity)
__device__ __half g_lnh[(size_t)MTOT*128];         // layernorm out, interleaved half
__device__ __half g_t3h[(size_t)MTOT*128];         // collapsed-mlp3 out
__device__ __half g_w9ph[9*8*128*32];              // conv weights [off][c8][co][32] interleaved
__device__ __half g_w1h [128*256];                 // mlp1 W^T [n][k-interleaved]
__device__ __half g_w3comb[128*128];
__device__ __half g_w4comb[128*128];
__device__ float  g_wtmp3[128*64];
__device__ float  g_wtmp4[128*64];
__device__ __half g_lnwh[(size_t)HWN*128];
__device__ __half g_lnbh[(size_t)HWN*128];
__device__ float  g_bias1[BATCH*128];
__device__ float  g_bias3c[BATCH*128];
__device__ float  g_bias4c[BATCH*128];
__device__ float  g_part[BATCH*512*2];
__device__ float  g_stats[BATCH*2];

// channel c (0..31) -> half slot within 32-half chunk (pair-interleaved)
__device__ __forceinline__ int lam32(int c){
    int g  = c >> 4;
    int kp = (c & 15) >> 1;
    int o  = c & 1;
    return 8*(kp & 3) + 4*g + 2*(kp >> 2) + o;
}

__device__ __forceinline__ void mma_fp16(float c[4],
        uint32_t a0, uint32_t a1, uint32_t a2, uint32_t a3,
        uint32_t b0, uint32_t b1){
    asm volatile(
        "mma.sync.aligned.m16n8k16.row.col.f32.f16.f16.f32 "
        "{%0,%1,%2,%3}, {%4,%5,%6,%7}, {%8,%9}, {%0,%1,%2,%3};"
        : "+f"(c[0]), "+f"(c[1]), "+f"(c[2]), "+f"(c[3])
        : "r"(a0), "r"(a1), "r"(a2), "r"(a3), "r"(b0), "r"(b1));
}

__device__ __forceinline__ void cp16(uint32_t dst, const void* src, int bytes){
    asm volatile("cp.async.cg.shared.global [%0], [%1], 16, %2;"
                 :: "r"(dst), "l"(src), "r"(bytes));
}
__device__ __forceinline__ void cp_commit(){ asm volatile("cp.async.commit_group;"); }
__device__ __forceinline__ void cp_wait1(){ asm volatile("cp.async.wait_group 1;"); }
__device__ __forceinline__ void cp_wait0(){ asm volatile("cp.async.wait_group 0;"); }

// ---------------- merged prep kernel 1 ----------------
__global__ void prep_all1(const float* __restrict__ cw,
                          const float* __restrict__ m1w, const float* __restrict__ m1b,
                          const float* __restrict__ sv,
                          const float* __restrict__ w31, const float* __restrict__ b31,
                          const float* __restrict__ w32, const float* __restrict__ b32,
                          const float* __restrict__ w33, const float* __restrict__ b33,
                          const float* __restrict__ w41, const float* __restrict__ b41,
                          const float* __restrict__ w42, const float* __restrict__ b42,
                          const float* __restrict__ w43, const float* __restrict__ b43,
                          const float* __restrict__ lnw, const float* __restrict__ lnb){
    int blk = blockIdx.x;
    int tid = threadIdx.x;

    if (blk < 1152){
        int i = blk*256 + tid;
        if (i < 9*8*128*32){
            int c   = i & 31;
            int co  = (i >> 5) & 127;
            int c8  = (i >> 12) & 7;
            int off = i >> 15;
            int ci  = c8*32 + c;
            g_w9ph[(((off*8 + c8)*128 + co)*32) + lam32(c)] =
                __float2half_rn(cw[(co*256 + ci)*9 + off]);
        }
    } else if (blk < 1280){
        int i = (blk - 1152)*256 + tid;
        int k = i & 255, n = i >> 8;
        g_w1h[n*256 + (k>>5)*32 + lam32(k & 31)] = __float2half_rn(m1w[k*128 + n]);
    } else if (blk < 1312){
        int i = (blk - 1280)*256 + tid;
        int k = i >> 6, j = i & 63;
        float s = 0.f;
        #pragma unroll 8
        for (int t = 0; t < 64; t++) s += w31[k*64 + t]*w32[t*64 + j];
        g_wtmp3[k*64 + j] = s;
    } else if (blk < 1344){
        int i = (blk - 1312)*256 + tid;
        int k = i >> 6, j = i & 63;
        float s = 0.f;
        #pragma unroll 8
        for (int t = 0; t < 64; t++) s += w41[k*64 + t]*w42[t*64 + j];
        g_wtmp4[k*64 + j] = s;
    } else if (blk < 1346){
        const float* w1 = (blk == 1344) ? w31 : w41;
        const float* b1 = (blk == 1344) ? b31 : b41;
        const float* w2 = (blk == 1344) ? w32 : w42;
        const float* b2 = (blk == 1344) ? b32 : b42;
        const float* w3 = (blk == 1344) ? w33 : w43;
        const float* b3 = (blk == 1344) ? b33 : b43;
        float* ob = (blk == 1344) ? g_bias3c : g_bias4c;
        __shared__ float v[64], u[64];
        int t = tid;
        for (int b = 0; b < BATCH; b++){
            float sb = sv[b];
            if (t < 64) v[t] = b1[t] + sb*w1[128*64 + t];
            __syncthreads();
            if (t < 64){
                float s = b2[t];
                #pragma unroll 8
                for (int i = 0; i < 64; i++) s += v[i]*w2[i*64 + t];
                u[t] = s;
            }
            __syncthreads();
            if (t < 128){
                float s = b3[t];
                #pragma unroll 8
                for (int j = 0; j < 64; j++) s += u[j]*w3[j*128 + t];
                ob[b*128 + t] = s;
            }
            __syncthreads();
        }
    } else if (blk == 1346){
        if (tid < 128)
            for (int b = 0; b < BATCH; b++)
                g_bias1[b*128+tid] = m1b[tid] + sv[b]*m1w[256*128 + tid];
    } else {
        size_t e = ((size_t)(blk - 1347)*256 + tid)*4;
        float4 w = *(const float4*)&lnw[e];
        float4 b = *(const float4*)&lnb[e];
        *(__half2*)(g_lnwh + e)     = __floats2half2_rn(w.x, w.y);
        *(__half2*)(g_lnwh + e + 2) = __floats2half2_rn(w.z, w.w);
        *(__half2*)(g_lnbh + e)     = __floats2half2_rn(b.x, b.y);
        *(__half2*)(g_lnbh + e + 2) = __floats2half2_rn(b.z, b.w);
    }
}

// ---------------- merged prep kernel 2 (combine_w3, depends on wtmp) ----------------
__global__ void prep_all2(const float* __restrict__ w33, const float* __restrict__ w43){
    int blk = blockIdx.x;
    int i = (blk & 63)*256 + threadIdx.x;
    int k = i >> 7, n = i & 127;
    const float* wt = (blk < 64) ? g_wtmp3 : g_wtmp4;
    const float* w3 = (blk < 64) ? w33 : w43;
    __half* o = (blk < 64) ? g_w3comb : g_w4comb;
    float s = 0.f;
    #pragma unroll 8
    for (int j = 0; j < 64; j++) s += wt[k*64 + j]*w3[j*128 + n];
    o[n*128 + (k>>5)*32 + lam32(k & 31)] = __float2half_rn(s);
}

// ---------------- fused bicubic 2x upsample -> interleaved half (g_xuPh) ----------------
__global__ __launch_bounds__(256) void upsample_fused_kernel(const float* __restrict__ x){
    __shared__ __half sm[2][256][32];
    int kh = blockIdx.x, c8 = blockIdx.y, b = blockIdx.z;
    int tid = threadIdx.x;
    int lane = tid & 31, warp = tid >> 5;

    int rr[5];
    #pragma unroll
    for (int i = 0; i < 5; i++){
        int r = kh - 2 + i; rr[i] = min(max(r,0),127);
    }
    const float we0=-0.03515625f, we1=0.26171875f, we2=0.87890625f, we3=-0.10546875f;
    const float wo0=-0.10546875f, wo1=0.87890625f, wo2=0.26171875f, wo3=-0.03515625f;

    #pragma unroll
    for (int q = 0; q < 4; q++){
        int cg = warp*4 + q;
        int c  = c8*32 + cg;
        const float* xp = x + ((size_t)(b*256 + c))*16384;
        int slot = lam32(cg);
        #pragma unroll
        for (int j = 0; j < 4; j++){
            int kw = lane + 32*j;
            int cc[5];
            #pragma unroll
            for (int i = 0; i < 5; i++){
                int cw_ = kw - 2 + i; cc[i] = min(max(cw_,0),127);
            }
            float he[5], ho[5];
            #pragma unroll
            for (int i = 0; i < 5; i++){
                const float* row = xp + rr[i]*128;
                float v0=row[cc[0]], v1=row[cc[1]], v2=row[cc[2]], v3=row[cc[3]], v4=row[cc[4]];
                he[i] = we0*v0 + we1*v1 + we2*v2 + we3*v3;
                ho[i] = wo0*v1 + wo1*v2 + wo2*v3 + wo3*v4;
            }
            float o00 = we0*he[0]+we1*he[1]+we2*he[2]+we3*he[3];
            float o01 = we0*ho[0]+we1*ho[1]+we2*ho[2]+we3*ho[3];
            float o10 = wo0*he[1]+wo1*he[2]+wo2*he[3]+wo3*he[4];
            float o11 = wo0*ho[1]+wo1*ho[2]+wo2*ho[3]+wo3*ho[4];
            sm[0][2*kw  ][slot] = __float2half_rn(o00);
            sm[0][2*kw+1][slot] = __float2half_rn(o01);
            sm[1][2*kw  ][slot] = __float2half_rn(o10);
            sm[1][2*kw+1][slot] = __float2half_rn(o11);
        }
    }
    __syncthreads();

    __half* out0 = g_xuPh + ((size_t)((b*256 + 2*kh    )*8 + c8))*8192;
    __half* out1 = g_xuPh + ((size_t)((b*256 + 2*kh + 1)*8 + c8))*8192;
    const uint4* s0 = (const uint4*)&sm[0][0][0];
    const uint4* s1 = (const uint4*)&sm[1][0][0];
    #pragma unroll
    for (int p = 0; p < 4; p++){
        ((uint4*)out0)[p*256 + tid] = s0[p*256 + tid];
        ((uint4*)out1)[p*256 + tid] = s1[p*256 + tid];
    }
}

// ---------------- y NCHW -> g_fh half (channels 128..255, interleaved slots) ----------------
__global__ void ycopy_kernel(const float* __restrict__ y){
    __shared__ float tile[32][33];
    int w0 = blockIdx.x*32, cb = blockIdx.y;
    int bh = blockIdx.z;
    int b = bh >> 8, h = bh & 255;
    int tx = threadIdx.x, ty = threadIdx.y;
    int c0 = cb*32;
    #pragma unroll
    for (int k = 0; k < 4; k++){
        int c = c0 + ty + k*8;
        tile[ty + k*8][tx] = y[(((size_t)b*128 + c)*256 + h)*256 + w0 + tx];
    }
    __syncthreads();
    int slot = (4 + cb)*32 + lam32(tx);
    #pragma unroll
    for (int k = 0; k < 4; k++){
        int w = w0 + ty + k*8;
        g_fh[(((size_t)b*256 + h)*256 + w)*256 + slot] = __float2half_rn(tile[tx][ty + k*8]);
    }
}

// ---------------- FUSED conv 3x3 + mlp1 (fp32 h1 out, B dbuf) ----------------
#define CM_SMEM 81920

__global__ __launch_bounds__(128, 2) void conv_mlp1_kernel(const float* __restrict__ convb){
    extern __shared__ char dsm[];
    __shared__ float shs[128], shs2[128];
    char* const Ab[2] = {dsm, dsm + 8320};
    char* const Bb[2] = {dsm + 16640, dsm + 41216};
    uint32_t Au[2], Bu[2];
    Au[0] = (uint32_t)__cvta_generic_to_shared(Ab[0]);
    Au[1] = (uint32_t)__cvta_generic_to_shared(Ab[1]);
    Bu[0] = (uint32_t)__cvta_generic_to_shared(Bb[0]);
    Bu[1] = (uint32_t)__cvta_generic_to_shared(Bb[1]);
    char* Am = dsm;                       // mlp1 A tile (8 chunks of 8192)
    uint32_t AmU = (uint32_t)__cvta_generic_to_shared(Am);
    char* const Bm[2] = {dsm + 65536, dsm + 73728};
    uint32_t BmU[2];
    BmU[0] = (uint32_t)__cvta_generic_to_shared(Bm[0]);
    BmU[1] = (uint32_t)__cvta_generic_to_shared(Bm[1]);

    int bx = blockIdx.x;
    int w0 = (bx & 1)*128;
    int h  = (bx >> 1) & 255;
    int b  = bx >> 9;
    int m0 = b*65536 + h*256 + w0;
    int tid = threadIdx.x;
    int wid = tid >> 5, lane = tid & 31;
    int wm = wid & 1, wn = wid >> 1;
    int lr = lane >> 2, lc = lane & 3;

    int hhs[3], off3s[3], nh = 0;
    #pragma unroll
    for (int dh = -1; dh <= 1; dh++){
        int hh = h + dh;
        if (hh >= 0 && hh < HH){ hhs[nh] = hh; off3s[nh] = (dh+1)*3; nh++; }
    }
    int nch = nh*8;

    float acc[4][8][4];
    #pragma unroll
    for (int mi = 0; mi < 4; mi++)
        #pragma unroll
        for (int ni = 0; ni < 8; ni++)
            #pragma unroll
            for (int r = 0; r < 4; r++) acc[mi][ni][r] = 0.f;

    auto fill = [&](int i, int s){
        int ih = i >> 3, c8 = i & 7;
        const __half* aplane = g_xuPh + ((size_t)((b*256 + hhs[ih])*8 + c8))*8192;
        #pragma unroll
        for (int p = 0; p < 5; p++){
            int idx = tid + p*128;
            if (idx < 520){
                int row = idx >> 2, t = idx & 3;
                int w_in = w0 - 1 + row;
                int ok = (w_in >= 0 && w_in < WWD) ? 16 : 0;
                int wc = min(max(w_in, 0), WWD-1);
                cp16(Au[s] + row*64 + (16*t ^ ((row & 1) << 5)),
                     aplane + wc*32 + t*8, ok);
            }
        }
        const __half* wb = g_w9ph + ((size_t)(off3s[ih]*8 + c8))*128*32;
        #pragma unroll
        for (int p = 0; p < 12; p++){
            int idx = tid + p*128;
            int row = idx >> 2, t = idx & 3;
            int dwi = row >> 7, co = row & 127;
            cp16(Bu[s] + row*64 + (16*t ^ ((row & 1) << 5)),
                 wb + ((size_t)dwi*8*128*32) + co*32 + t*8, 16);
        }
    };

    // ===== conv mainloop =====
    fill(0, 0);
    cp_commit();

    for (int i = 0; i < nch; i++){
        int s = i & 1;
        if (i + 1 < nch){ fill(i+1, s^1); cp_commit(); cp_wait1(); }
        else cp_wait0();
        __syncthreads();

        char* As = Ab[s];
        char* Bs = Bb[s];
        #pragma unroll
        for (int dwi = 0; dwi < 3; dwi++){
            uint4 bf[8];
            #pragma unroll
            for (int ni = 0; ni < 8; ni++){
                int brow = dwi*128 + wn*64 + ni*8 + lr;
                bf[ni] = *(const uint4*)(Bs + brow*64 + (16*lc ^ ((brow & 1) << 5)));
            }
            #pragma unroll
            for (int mi = 0; mi < 4; mi++){
                int ar0 = wm*64 + mi*16 + lr + dwi;
                int ar1 = ar0 + 8;
                uint4 A1 = *(const uint4*)(As + ar0*64 + (16*lc ^ ((ar0 & 1) << 5)));
                uint4 A2 = *(const uint4*)(As + ar1*64 + (16*lc ^ ((ar1 & 1) << 5)));
                #pragma unroll
                for (int ni = 0; ni < 8; ni++){
                    mma_fp16(acc[mi][ni], A1.x, A2.x, A1.y, A2.y, bf[ni].x, bf[ni].y);
                    mma_fp16(acc[mi][ni], A1.z, A2.z, A1.w, A2.w, bf[ni].z, bf[ni].w);
                }
            }
        }
        __syncthreads();
    }

    // ===== stage conv result as mlp1 A chunks 0..3; cp.async y-half to chunks 4..7 =====
    #pragma unroll
    for (int p = 0; p < 16; p++){
        int idx = tid + p*128;
        int ch  = 4 + (idx >> 9);
        int rem = idx & 511;
        int row = rem >> 2, t = rem & 3;
        cp16(AmU + ch*8192 + row*64 + (16*t ^ ((row & 1) << 5)),
             g_fh + ((size_t)(m0 + row)*256 + ch*32) + t*8, 16);
    }
    cp_commit();

    {
        float bv0[8], bv1[8];
        #pragma unroll
        for (int ni = 0; ni < 8; ni++){
            int n = wn*64 + ni*8 + lc*2;
            bv0[ni] = convb[n];
            bv1[ni] = convb[n+1];
        }
        #pragma unroll
        for (int mi = 0; mi < 4; mi++){
            int r0 = wm*64 + mi*16 + lr;
            int r1 = r0 + 8;
            int sw0 = (r0 & 1) << 5, sw1 = (r1 & 1) << 5;
            #pragma unroll
            for (int ni = 0; ni < 8; ni++){
                int n = wn*64 + ni*8 + lc*2;
                int ch = n >> 5;
                int sl = 2*lam32(n & 31);
                *(__half2*)(Am + ch*8192 + r0*64 + (sl ^ sw0)) =
                    __floats2half2_rn(acc[mi][ni][0] + bv0[ni], acc[mi][ni][1] + bv1[ni]);
                *(__half2*)(Am + ch*8192 + r1*64 + (sl ^ sw1)) =
                    __floats2half2_rn(acc[mi][ni][2] + bv0[ni], acc[mi][ni][3] + bv1[ni]);
            }
        }
    }
    cp_wait0();
    __syncthreads();

    // ===== mlp1: h1 = relu(A @ w1h + bias1), A resident, B double-buffered =====
    #pragma unroll
    for (int mi = 0; mi < 4; mi++)
        #pragma unroll
        for (int ni = 0; ni < 8; ni++)
            #pragma unroll
            for (int r = 0; r < 4; r++) acc[mi][ni][r] = 0.f;

    auto fillB = [&](int chunk, int s){
        #pragma unroll
        for (int p = 0; p < 4; p++){
            int idx = tid + p*128;
            int row = idx >> 2, t = idx & 3;
            cp16(BmU[s] + row*64 + (16*t ^ ((row & 1) << 5)),
                 g_w1h + (row*256 + chunk*32) + t*8, 16);
        }
    };

    fillB(0, 0);
    cp_commit();

    for (int chunk = 0; chunk < 8; chunk++){
        int s = chunk & 1;
        if (chunk + 1 < 8){ fillB(chunk+1, s^1); cp_commit(); cp_wait1(); }
        else cp_wait0();
        __syncthreads();

        char* Ac = Am + chunk*8192;
        uint4 bf[8];
        #pragma unroll
        for (int ni = 0; ni < 8; ni++){
            int brow = wn*64 + ni*8 + lr;
            bf[ni] = *(const uint4*)(Bm[s] + brow*64 + (16*lc ^ ((brow & 1) << 5)));
        }
        #pragma unroll
        for (int mi = 0; mi < 4; mi++){
            int ar0 = wm*64 + mi*16 + lr;
            int ar1 = ar0 + 8;
            uint4 A1 = *(const uint4*)(Ac + ar0*64 + (16*lc ^ ((ar0 & 1) << 5)));
            uint4 A2 = *(const uint4*)(Ac + ar1*64 + (16*lc ^ ((ar1 & 1) << 5)));
            #pragma unroll
            for (int ni = 0; ni < 8; ni++){
                mma_fp16(acc[mi][ni], A1.x, A2.x, A1.y, A2.y, bf[ni].x, bf[ni].y);
                mma_fp16(acc[mi][ni], A1.z, A2.z, A1.w, A2.w, bf[ni].z, bf[ni].w);
            }
        }
        __syncthreads();
    }

    // epilogue: per-batch bias + relu -> h1 fp32 + LN partial sums
    {
        float bv0[8], bv1[8];
        #pragma unroll
        for (int ni = 0; ni < 8; ni++){
            int n = wn*64 + ni*8 + lc*2;
            bv0[ni] = g_bias1[b*128 + n];
            bv1[ni] = g_bias1[b*128 + n + 1];
        }
        float ts = 0.f, ts2 = 0.f;
        #pragma unroll
        for (int mi = 0; mi < 4; mi++){
            int mr = m0 + wm*64 + mi*16 + lr;
            float* dst0 = g_h1 + (size_t)mr*128;
            float* dst1 = g_h1 + (size_t)(mr + 8)*128;
            #pragma unroll
            for (int ni = 0; ni < 8; ni++){
                int n = wn*64 + ni*8 + lc*2;
                float v0 = fmaxf(acc[mi][ni][0] + bv0[ni], 0.f);
                float v1 = fmaxf(acc[mi][ni][1] + bv1[ni], 0.f);
                float v2 = fmaxf(acc[mi][ni][2] + bv0[ni], 0.f);
                float v3 = fmaxf(acc[mi][ni][3] + bv1[ni], 0.f);
                *(float2*)(dst0 + n) = make_float2(v0, v1);
                *(float2*)(dst1 + n) = make_float2(v2, v3);
                ts  += v0 + v1 + v2 + v3;
                ts2 += v0*v0 + v1*v1 + v2*v2 + v3*v3;
            }
        }
        shs[tid] = ts; shs2[tid] = ts2;
        __syncthreads();
        for (int st = 64; st > 0; st >>= 1){
            if (tid < st){ shs[tid] += shs[tid+st]; shs2[tid] += shs2[tid+st]; }
            __syncthreads();
        }
        if (tid == 0){
            int cta = (m0 >> 7) & 511;
            g_part[(b*512 + cta)*2    ] = shs[0];
            g_part[(b*512 + cta)*2 + 1] = shs2[0];
        }
    }
}

// ---------------- layernorm finish ----------------
__global__ void ln_finish(){
    int b = blockIdx.x, tid = threadIdx.x;
    float s = 0.f, s2 = 0.f;
    for (int i = tid; i < 512; i += 256){
        s  += g_part[(b*512 + i)*2];
        s2 += g_part[(b*512 + i)*2 + 1];
    }
    __shared__ float sh[256], sh2[256];
    sh[tid] = s; sh2[tid] = s2; __syncthreads();
    for (int st = 128; st > 0; st >>= 1){
        if (tid < st){ sh[tid] += sh[tid+st]; sh2[tid] += sh2[tid+st]; }
        __syncthreads();
    }
    if (tid == 0){
        const float invN = 1.f / 8388608.f;
        float mu  = sh[0] * invN;
        float var = sh2[0] * invN - mu*mu;
        g_stats[b*2]     = mu;
        g_stats[b*2 + 1] = rsqrtf(var + 1e-5f);
    }
}

// ---------------- ln apply (h1 fp32 in) -> half interleaved ----------------
__global__ void ln_apply(){
    size_t e = ((size_t)blockIdx.x*256 + threadIdx.x)*4;
    int b = (int)(e >> 23);
    float mu = g_stats[b*2], rs = g_stats[b*2 + 1];
    size_t li = e & 8388607u;
    int m = (int)(e >> 7);
    int c = (int)(e & 127);
    float4 h = *(const float4*)&g_h1[e];
    float2 wf0 = __half22float2(*(const __half2*)(g_lnwh + li));
    float2 wf1 = __half22float2(*(const __half2*)(g_lnwh + li + 2));
    float2 bf0 = __half22float2(*(const __half2*)(g_lnbh + li));
    float2 bf1 = __half22float2(*(const __half2*)(g_lnbh + li + 2));
    float o0 = (h.x - mu)*rs*wf0.x + bf0.x;
    float o1 = (h.y - mu)*rs*wf0.y + bf0.y;
    float o2 = (h.z - mu)*rs*wf1.x + bf1.x;
    float o3 = (h.w - mu)*rs*wf1.y + bf1.y;
    __half* dst = g_lnh + (size_t)m*128;
    int s0 = (c >> 5)*32 + lam32(c & 31);
    int s1 = ((c+2) >> 5)*32 + lam32((c+2) & 31);
    *(__half2*)(dst + s0) = __floats2half2_rn(o0, o1);
    *(__half2*)(dst + s1) = __floats2half2_rn(o2, o3);
}

// ---------------- collapsed-chain fp16 GEMM: K=128, N=128 ----------------
template<int EPI>
__global__ __launch_bounds__(128, 2) void hgemm2_kernel(
    const __half* __restrict__ A, const __half* __restrict__ Bw,
    const float* __restrict__ biasPB,
    __half* __restrict__ outh, float* __restrict__ outf,
    const float* __restrict__ identity)
{
    __shared__ __align__(16) char As[128*64];
    __shared__ __align__(16) char Bs[128*64];

    int m0  = blockIdx.x*128;
    int tid = threadIdx.x;
    int wid = tid >> 5, lane = tid & 31;
    int wm = wid & 1, wn = wid >> 1;
    int lr = lane >> 2, lc = lane & 3;

    float acc[4][8][4];
    #pragma unroll
    for (int mi = 0; mi < 4; mi++)
        #pragma unroll
        for (int ni = 0; ni < 8; ni++)
            #pragma unroll
            for (int r = 0; r < 4; r++) acc[mi][ni][r] = 0.f;

    #pragma unroll
    for (int chunk = 0; chunk < 4; chunk++){
        if (chunk) __syncthreads();
        #pragma unroll
        for (int p = 0; p < 4; p++){
            int idx = tid + p*128;
            int row = idx >> 2, t = idx & 3;
            uint32_t sw = 16*t ^ ((row & 1) << 5);
            uint4 va = *(const uint4*)(A + ((size_t)(m0 + row)*128 + chunk*32) + t*8);
            *(uint4*)(As + row*64 + sw) = va;
            uint4 vb = *(const uint4*)(Bw + ((size_t)row*128 + chunk*32) + t*8);
            *(uint4*)(Bs + row*64 + sw) = vb;
        }
        __syncthreads();

        uint4 bf[8];
        #pragma unroll
        for (int ni = 0; ni < 8; ni++){
            int brow = wn*64 + ni*8 + lr;
            bf[ni] = *(const uint4*)(Bs + brow*64 + (16*lc ^ ((brow & 1) << 5)));
        }
        #pragma unroll
        for (int mi = 0; mi < 4; mi++){
            int ar0 = wm*64 + mi*16 + lr;
            int ar1 = ar0 + 8;
            uint4 A1 = *(const uint4*)(As + ar0*64 + (16*lc ^ ((ar0 & 1) << 5)));
            uint4 A2 = *(const uint4*)(As + ar1*64 + (16*lc ^ ((ar1 & 1) << 5)));
            #pragma unroll
            for (int ni = 0; ni < 8; ni++){
                mma_fp16(acc[mi][ni], A1.x, A2.x, A1.y, A2.y, bf[ni].x, bf[ni].y);
                mma_fp16(acc[mi][ni], A1.z, A2.z, A1.w, A2.w, bf[ni].z, bf[ni].w);
            }
        }
    }

    int b = m0 >> 16;
    const float* bp = biasPB + b*128;
    float bv0[8], bv1[8];
    int slot[8];
    #pragma unroll
    for (int ni = 0; ni < 8; ni++){
        int n = wn*64 + ni*8 + lc*2;
        bv0[ni] = bp[n];
        bv1[ni] = bp[n+1];
        slot[ni] = (n >> 5)*32 + lam32(n & 31);
    }

    #pragma unroll
    for (int mi = 0; mi < 4; mi++){
        int mr = m0 + wm*64 + mi*16 + lr;
        if constexpr (EPI == 1){
            int hw0 = mr & 65535, hw1 = (mr + 8) & 65535;
            const float* id0 = identity + (size_t)mr*128;
            const float* id1 = identity + (size_t)(mr + 8)*128;
            #pragma unroll
            for (int ni = 0; ni < 8; ni++){
                int n = wn*64 + ni*8 + lc*2;
                float* o0 = outf + ((size_t)(b*128 + n))*65536;
                float* o1 = outf + ((size_t)(b*128 + n + 1))*65536;
                o0[hw0] = fmaxf(acc[mi][ni][0] + bv0[ni], 0.f) + id0[n];
                o1[hw0] = fmaxf(acc[mi][ni][1] + bv1[ni], 0.f) + id0[n+1];
                o0[hw1] = fmaxf(acc[mi][ni][2] + bv0[ni], 0.f) + id1[n];
                o1[hw1] = fmaxf(acc[mi][ni][3] + bv1[ni], 0.f) + id1[n+1];
            }
        } else {
            __half* dst0 = outh + (size_t)mr*128;
            __half* dst1 = outh + (size_t)(mr + 8)*128;
            #pragma unroll
            for (int ni = 0; ni < 8; ni++){
                *(__half2*)(dst0 + slot[ni]) =
                    __floats2half2_rn(fmaxf(acc[mi][ni][0] + bv0[ni], 0.f),
                                      fmaxf(acc[mi][ni][1] + bv1[ni], 0.f));
                *(__half2*)(dst1 + slot[ni]) =
                    __floats2half2_rn(fmaxf(acc[mi][ni][2] + bv0[ni], 0.f),
                                      fmaxf(acc[mi][ni][3] + bv1[ni], 0.f));
            }
        }
    }
}

// ---------------- launch ----------------
extern "C" void kernel_launch(void* const* d_in, const int* in_sizes, int n_in,
                              void* d_out, int out_size){
    const float* x      = (const float*)d_in[0];
    const float* y      = (const float*)d_in[1];
    const float* s      = (const float*)d_in[2];
    const float* conv_w = (const float*)d_in[4];
    const float* conv_b = (const float*)d_in[5];
    const float* mlp1_w = (const float*)d_in[6];
    const float* mlp1_b = (const float*)d_in[7];
    const float* ln_w   = (const float*)d_in[8];
    const float* ln_b   = (const float*)d_in[9];
    const float* m3_w1  = (const float*)d_in[10];
    const float* m3_b1  = (const float*)d_in[11];
    const float* m3_w2  = (const float*)d_in[12];
    const float* m3_b2  = (const float*)d_in[13];
    const float* m3_w3  = (const float*)d_in[14];
    const float* m3_b3  = (const float*)d_in[15];
    const float* m4_w1  = (const float*)d_in[16];
    const float* m4_b1  = (const float*)d_in[17];
    const float* m4_w2  = (const float*)d_in[18];
    const float* m4_b2  = (const float*)d_in[19];
    const float* m4_w3  = (const float*)d_in[20];
    const float* m4_b3  = (const float*)d_in[21];
    float* out = (float*)d_out;

    cudaFuncSetAttribute(conv_mlp1_kernel,
                         cudaFuncAttributeMaxDynamicSharedMemorySize, CM_SMEM);

    void *ph1, *plnh, *pt3, *pw3c, *pw4c, *pb3c, *pb4c;
    cudaGetSymbolAddress(&ph1, g_h1);
    cudaGetSymbolAddress(&plnh, g_lnh);
    cudaGetSymbolAddress(&pt3, g_t3h);
    cudaGetSymbolAddress(&pw3c, g_w3comb);
    cudaGetSymbolAddress(&pw4c, g_w4comb);
    cudaGetSymbolAddress(&pb3c, g_bias3c);
    cudaGetSymbolAddress(&pb4c, g_bias4c);

    prep_all1<<<9539, 256>>>(conv_w, mlp1_w, mlp1_b, s,
                             m3_w1, m3_b1, m3_w2, m3_b2, m3_w3, m3_b3,
                             m4_w1, m4_b1, m4_w2, m4_b2, m4_w3, m4_b3,
                             ln_w, ln_b);
    prep_all2<<<128, 256>>>(m3_w3, m4_w3);

    upsample_fused_kernel<<<dim3(128, 8, 8), 256>>>(x);
    ycopy_kernel<<<dim3(8, 4, 2048), dim3(32, 8)>>>(y);
    conv_mlp1_kernel<<<4096, 128, CM_SMEM>>>(conv_b);

    ln_finish<<<8, 256>>>();
    ln_apply<<<65536, 256>>>();

    hgemm2_kernel<0><<<4096, 128>>>((const __half*)plnh, (const __half*)pw3c,
                                    (const float*)pb3c, (__half*)pt3, nullptr, nullptr);
    hgemm2_kernel<1><<<4096, 128>>>((const __half*)pt3, (const __half*)pw4c,
                                    (const float*)pb4c, nullptr, out, (const float*)ph1);
}